// round 8
// baseline (speedup 1.0000x reference)
#include <cuda_runtime.h>
#include <cuda_bf16.h>
#include <cstdint>

#define N_NODES 50000
#define N_EDGES 800000
#define IN_CH   256
#define OUT_CH  64
#define NEG_SLOPE 0.2f

// ---------------- scratch (device globals; no allocations allowed) -------------
__device__ float    g_feature[N_NODES * OUT_CH];
__device__ float    g_e0[N_NODES];
__device__ float    g_e1[N_NODES];
__device__ float    g_es[N_NODES];          // exp(self logit)
__device__ uint32_t g_Wh[2 * 64 * 64];      // [half][n][kw] bf16x2 hi
__device__ uint32_t g_Wl[2 * 64 * 64];      // [half][n][kw] bf16x2 lo
__device__ int      g_cnt[N_NODES];         // in-degree histogram
__device__ int      g_rowptr[N_NODES + 1];  // CSR row pointers
__device__ int      g_cursor[N_NODES];      // scatter cursors
__device__ int      g_csrc[N_EDGES];        // CSR: src node per slot

__device__ __forceinline__ float lrelu(float v) {
    return v > 0.0f ? v : NEG_SLOPE * v;
}

// pack two floats (even, odd) into bf16x2 (even in low half)
__device__ __forceinline__ uint32_t pack_bf16(float e, float o) {
    uint32_t d;
    asm("cvt.rn.bf16x2.f32 %0, %1, %2;" : "=r"(d) : "f"(o), "f"(e));
    return d;
}
__device__ __forceinline__ float bf16lo_val(uint32_t w) { return __uint_as_float(w << 16); }
__device__ __forceinline__ float bf16hi_val(uint32_t w) { return __uint_as_float(w & 0xFFFF0000u); }

// m16n8k16 row.col bf16 HMMA (target-generic; tcgen05 unavailable on this build)
__device__ __forceinline__ void mma_bf16(float* c, const uint32_t* a, uint32_t b0, uint32_t b1) {
    asm volatile(
        "mma.sync.aligned.m16n8k16.row.col.f32.bf16.bf16.f32 "
        "{%0,%1,%2,%3}, {%4,%5,%6,%7}, {%8,%9}, {%0,%1,%2,%3};"
        : "+f"(c[0]), "+f"(c[1]), "+f"(c[2]), "+f"(c[3])
        : "r"(a[0]), "r"(a[1]), "r"(a[2]), "r"(a[3]), "r"(b0), "r"(b1));
}

// ------------- K0: one-time W -> bf16 hi/lo conversion + histogram zero --------
__global__ __launch_bounds__(256) void k_wconv(const float* __restrict__ W) {
    int idx = blockIdx.x * 256 + threadIdx.x;    // 0..8191
    int half = idx >> 12, rem = idx & 4095;
    int n = rem >> 6, j = rem & 63;
    int k = half * 128 + j * 2;
    float w0 = W[n * 256 + k], w1 = W[n * 256 + k + 1];
    uint32_t h = pack_bf16(w0, w1);
    uint32_t l = pack_bf16(w0 - bf16lo_val(h), w1 - bf16hi_val(h));
    g_Wh[idx] = h;
    g_Wl[idx] = l;
    // zero the histogram (grid-stride; 8192 threads cover 50000)
    for (int i = idx; i < N_NODES; i += 8192) g_cnt[i] = 0;
}

// ------------- K1: HMMA bf16 hi/lo projection, single x pass -------------------
__global__ __launch_bounds__(128, 5) void k_gemm_tc(const float* __restrict__ x,
                                                    const float* __restrict__ b,
                                                    const float* __restrict__ att) {
    __shared__ __align__(16) uint32_t sBh[64][68];
    __shared__ __align__(16) uint32_t sBl[64][68];

    const int tid  = threadIdx.x;
    const int wid  = tid >> 5;
    const int lane = tid & 31;
    const int g    = lane >> 2;       // 0..7
    const int tig  = lane & 3;        // 0..3

    const int base = blockIdx.x * 64 + wid * 16;
    const int r0 = base + g;
    const int r1 = base + g + 8;
    const bool v0 = r0 < N_NODES;
    const bool v1 = r1 < N_NODES;
    const float* xr0 = x + (size_t)(v0 ? r0 : 0) * IN_CH;
    const float* xr1 = x + (size_t)(v1 ? r1 : 0) * IN_CH;

    float acc[8][4];
#pragma unroll
    for (int nt = 0; nt < 8; nt++)
#pragma unroll
        for (int i = 0; i < 4; i++) acc[nt][i] = 0.f;

    const int cn   = tid >> 1;
    const int part = tid & 1;

#pragma unroll
    for (int half = 0; half < 2; half++) {
        if (half) __syncthreads();
        {
            const uint4* srcH = (const uint4*)&g_Wh[half * 4096 + cn * 64 + part * 32];
            const uint4* srcL = (const uint4*)&g_Wl[half * 4096 + cn * 64 + part * 32];
            uint4* dstH = (uint4*)&sBh[cn][part * 32];
            uint4* dstL = (uint4*)&sBl[cn][part * 32];
#pragma unroll
            for (int i = 0; i < 8; i++) { dstH[i] = srcH[i]; dstL[i] = srcL[i]; }
        }
        __syncthreads();

#pragma unroll
        for (int kc = 0; kc < 8; kc++) {
            const int k0 = half * 128 + kc * 16 + tig * 2;
            float2 a0 = *(const float2*)(xr0 + k0);
            float2 a4 = *(const float2*)(xr0 + k0 + 8);
            float2 c0 = *(const float2*)(xr1 + k0);
            float2 c4 = *(const float2*)(xr1 + k0 + 8);
            uint32_t ah[4], al[4];
            ah[0] = pack_bf16(a0.x, a0.y);
            ah[1] = pack_bf16(c0.x, c0.y);
            ah[2] = pack_bf16(a4.x, a4.y);
            ah[3] = pack_bf16(c4.x, c4.y);
            al[0] = pack_bf16(a0.x - bf16lo_val(ah[0]), a0.y - bf16hi_val(ah[0]));
            al[1] = pack_bf16(c0.x - bf16lo_val(ah[1]), c0.y - bf16hi_val(ah[1]));
            al[2] = pack_bf16(a4.x - bf16lo_val(ah[2]), a4.y - bf16hi_val(ah[2]));
            al[3] = pack_bf16(c4.x - bf16lo_val(ah[3]), c4.y - bf16hi_val(ah[3]));
#pragma unroll
            for (int nt = 0; nt < 8; nt++) {
                const int n = nt * 8 + g;
                const int kw = kc * 8 + tig;
                uint32_t bh0 = sBh[n][kw], bh1 = sBh[n][kw + 4];
                uint32_t bl0 = sBl[n][kw], bl1 = sBl[n][kw + 4];
                mma_bf16(acc[nt], ah, bh0, bh1);
                mma_bf16(acc[nt], al, bh0, bh1);
                mma_bf16(acc[nt], ah, bl0, bl1);
            }
        }
    }

    // ---- epilogue: bias into acc, e0/e1 reduce, feature + self exp stores ----
    float e0a = 0.f, e1a = 0.f, e0b = 0.f, e1b = 0.f;
#pragma unroll
    for (int nt = 0; nt < 8; nt++) {
        int col = nt * 8 + tig * 2;
        float bi0 = __ldg(&b[col]);
        float bi1 = __ldg(&b[col + 1]);
        float at00 = __ldg(&att[col * 2 + 0]),   at01 = __ldg(&att[col * 2 + 1]);
        float at10 = __ldg(&att[(col + 1) * 2]), at11 = __ldg(&att[(col + 1) * 2 + 1]);
        acc[nt][0] += bi0; acc[nt][1] += bi1;
        acc[nt][2] += bi0; acc[nt][3] += bi1;
        e0a += acc[nt][0] * at00 + acc[nt][1] * at10;
        e1a += acc[nt][0] * at01 + acc[nt][1] * at11;
        e0b += acc[nt][2] * at00 + acc[nt][3] * at10;
        e1b += acc[nt][2] * at01 + acc[nt][3] * at11;
    }
#pragma unroll
    for (int o = 1; o <= 2; o <<= 1) {
        e0a += __shfl_xor_sync(0xffffffffu, e0a, o);
        e1a += __shfl_xor_sync(0xffffffffu, e1a, o);
        e0b += __shfl_xor_sync(0xffffffffu, e0b, o);
        e1b += __shfl_xor_sync(0xffffffffu, e1b, o);
    }
#pragma unroll
    for (int nt = 0; nt < 8; nt++) {
        int col = nt * 8 + tig * 2;
        if (v0) *(float2*)&g_feature[(size_t)r0 * OUT_CH + col] = make_float2(acc[nt][0], acc[nt][1]);
        if (v1) *(float2*)&g_feature[(size_t)r1 * OUT_CH + col] = make_float2(acc[nt][2], acc[nt][3]);
    }
    if (tig == 0) {
        if (v0) { g_e0[r0] = e0a; g_e1[r0] = e1a; g_es[r0] = __expf(lrelu(e0a + e1a)); }
        if (v1) { g_e0[r1] = e0b; g_e1[r1] = e1b; g_es[r1] = __expf(lrelu(e0b + e1b)); }
    }
}

// ------------- K2a: in-degree histogram ----------------------------------------
__global__ __launch_bounds__(256) void k_hist(const int* __restrict__ ei) {
    int e = blockIdx.x * 256 + threadIdx.x;
    if (e >= N_EDGES) return;
    atomicAdd(&g_cnt[__ldg(&ei[e])], 1);
}

// ------------- K2b: single-block exclusive scan -> rowptr + cursors ------------
#define SCAN_T 1024
#define CHUNK  49   // 1024*49 = 50176 >= 50000
__global__ __launch_bounds__(SCAN_T) void k_scan() {
    __shared__ int part[SCAN_T];
    const int t = threadIdx.x;
    const int beg = t * CHUNK;
    const int end = min(beg + CHUNK, N_NODES);
    int s = 0;
    for (int i = beg; i < end; i++) s += g_cnt[i];
    part[t] = s;
    __syncthreads();
    // Hillis-Steele inclusive scan
    for (int o = 1; o < SCAN_T; o <<= 1) {
        int v = (t >= o) ? part[t - o] : 0;
        __syncthreads();
        part[t] += v;
        __syncthreads();
    }
    int run = (t == 0) ? 0 : part[t - 1];
    for (int i = beg; i < end; i++) {
        g_rowptr[i] = run;
        g_cursor[i] = run;
        run += g_cnt[i];
    }
    if (t == SCAN_T - 1) g_rowptr[N_NODES] = run;
}

// ------------- K2c: scatter src indices into CSR slots -------------------------
__global__ __launch_bounds__(256) void k_scatter(const int* __restrict__ ei) {
    int e = blockIdx.x * 256 + threadIdx.x;
    if (e >= N_EDGES) return;
    int tar = __ldg(&ei[e]);
    int src = __ldg(&ei[N_EDGES + e]);
    int pos = atomicAdd(&g_cursor[tar], 1);
    g_csrc[pos] = src;
}

// ------------- K3: pull-mode aggregation (warp per node, register acc) ---------
// Lanes own 2 channels. Batch 32 edges: lane j computes ee_j; broadcast + FMA.
// Denominator accumulates in-register -> no RED, no normalize pass.
__global__ __launch_bounds__(256) void k_agg(float* __restrict__ out) {
    const int warp = (blockIdx.x * 256 + threadIdx.x) >> 5;
    const int lane = threadIdx.x & 31;
    if (warp >= N_NODES) return;
    const int n = warp;
    const int beg = g_rowptr[n];
    const int end = g_rowptr[n + 1];
    const float e0n = g_e0[n];
    const float es  = g_es[n];
    float2 fs = *(const float2*)&g_feature[(size_t)n * OUT_CH + lane * 2];
    float acc0 = es * fs.x, acc1 = es * fs.y, dsum = es;

    for (int j0 = beg; j0 < end; j0 += 32) {
        const int idx = j0 + lane;
        int src = 0;
        float ee = 0.f;
        if (idx < end) {
            src = __ldg(&g_csrc[idx]);
            ee  = __expf(lrelu(e0n + __ldg(&g_e1[src])));
        }
        const int cnt = min(32, end - j0);
        for (int j = 0; j < cnt; j++) {
            int   s = __shfl_sync(0xffffffffu, src, j);
            float w = __shfl_sync(0xffffffffu, ee,  j);
            float2 f = *(const float2*)&g_feature[(size_t)s * OUT_CH + lane * 2];
            acc0 += w * f.x;
            acc1 += w * f.y;
            dsum += w;
        }
    }
    const float rd = 1.0f / dsum;
    *(float2*)&out[(size_t)n * OUT_CH + lane * 2] = make_float2(acc0 * rd, acc1 * rd);
}

// -------------------------------------------------------------------------------
extern "C" void kernel_launch(void* const* d_in, const int* in_sizes, int n_in,
                              void* d_out, int out_size) {
    const float* x   = (const float*)d_in[0];
    const int*   ei  = (const int*)d_in[1];   // int32 (JAX x64 disabled)
    const float* W   = (const float*)d_in[2];
    const float* b   = (const float*)d_in[3];
    const float* att = (const float*)d_in[4];
    float* out = (float*)d_out;

    // K0: W -> bf16 hi/lo + histogram zero
    k_wconv<<<32, 256>>>(W);
    // K2a: in-degree histogram (independent of gemm; runs first to overlap nothing, cheap)
    k_hist<<<(N_EDGES + 255) / 256, 256>>>(ei);
    // K1: HMMA projection + attention pre-terms
    k_gemm_tc<<<(N_NODES + 63) / 64, 128>>>(x, b, att);
    // K2b: scan -> rowptr/cursors
    k_scan<<<1, SCAN_T>>>();
    // K2c: scatter src ids
    k_scatter<<<(N_EDGES + 255) / 256, 256>>>(ei);
    // K3: pull aggregation + in-register softmax denominator
    k_agg<<<(N_NODES * 32 + 255) / 256, 256>>>(out);
}

// round 9
// speedup vs baseline: 1.8354x; 1.8354x over previous
#include <cuda_runtime.h>
#include <cuda_bf16.h>
#include <cstdint>

#define N_NODES 50000
#define N_EDGES 800000
#define IN_CH   256
#define OUT_CH  64
#define NEG_SLOPE 0.2f
#define NB_SCAN 196   // ceil(N_NODES/256)

// ---------------- scratch (device globals; no allocations allowed) -------------
__device__ float    g_feature[N_NODES * OUT_CH];
__device__ float    g_e0[N_NODES];
__device__ float    g_e1[N_NODES];
__device__ float    g_es[N_NODES];          // exp(self logit)
__device__ uint32_t g_Wh[2 * 64 * 64];      // [half][n][kw] bf16x2 hi
__device__ uint32_t g_Wl[2 * 64 * 64];      // [half][n][kw] bf16x2 lo
__device__ int      g_cnt[N_NODES];         // in-degree histogram
__device__ int      g_rowptr[N_NODES + 1];  // CSR row pointers
__device__ int      g_cursor[N_NODES];      // scatter cursors
__device__ int      g_csrc[N_EDGES];        // CSR: src node per slot
__device__ int      g_bsum[NB_SCAN];        // per-block count sums
__device__ int      g_boff[NB_SCAN];        // exclusive block offsets

__device__ __forceinline__ float lrelu(float v) {
    return v > 0.0f ? v : NEG_SLOPE * v;
}

// pack two floats (even, odd) into bf16x2 (even in low half)
__device__ __forceinline__ uint32_t pack_bf16(float e, float o) {
    uint32_t d;
    asm("cvt.rn.bf16x2.f32 %0, %1, %2;" : "=r"(d) : "f"(o), "f"(e));
    return d;
}
__device__ __forceinline__ float bf16lo_val(uint32_t w) { return __uint_as_float(w << 16); }
__device__ __forceinline__ float bf16hi_val(uint32_t w) { return __uint_as_float(w & 0xFFFF0000u); }

// m16n8k16 row.col bf16 HMMA (target-generic; tcgen05 unavailable on this build)
__device__ __forceinline__ void mma_bf16(float* c, const uint32_t* a, uint32_t b0, uint32_t b1) {
    asm volatile(
        "mma.sync.aligned.m16n8k16.row.col.f32.bf16.bf16.f32 "
        "{%0,%1,%2,%3}, {%4,%5,%6,%7}, {%8,%9}, {%0,%1,%2,%3};"
        : "+f"(c[0]), "+f"(c[1]), "+f"(c[2]), "+f"(c[3])
        : "r"(a[0]), "r"(a[1]), "r"(a[2]), "r"(a[3]), "r"(b0), "r"(b1));
}

// ------------- K0: one-time W -> bf16 hi/lo conversion + histogram zero --------
__global__ __launch_bounds__(256) void k_wconv(const float* __restrict__ W) {
    int idx = blockIdx.x * 256 + threadIdx.x;    // 0..8191
    int half = idx >> 12, rem = idx & 4095;
    int n = rem >> 6, j = rem & 63;
    int k = half * 128 + j * 2;
    float w0 = W[n * 256 + k], w1 = W[n * 256 + k + 1];
    uint32_t h = pack_bf16(w0, w1);
    uint32_t l = pack_bf16(w0 - bf16lo_val(h), w1 - bf16hi_val(h));
    g_Wh[idx] = h;
    g_Wl[idx] = l;
    for (int i = idx; i < N_NODES; i += 8192) g_cnt[i] = 0;
}

// ------------- K1: HMMA bf16 hi/lo projection, single x pass -------------------
__global__ __launch_bounds__(128, 5) void k_gemm_tc(const float* __restrict__ x,
                                                    const float* __restrict__ b,
                                                    const float* __restrict__ att) {
    __shared__ __align__(16) uint32_t sBh[64][68];
    __shared__ __align__(16) uint32_t sBl[64][68];

    const int tid  = threadIdx.x;
    const int wid  = tid >> 5;
    const int lane = tid & 31;
    const int g    = lane >> 2;       // 0..7
    const int tig  = lane & 3;        // 0..3

    const int base = blockIdx.x * 64 + wid * 16;
    const int r0 = base + g;
    const int r1 = base + g + 8;
    const bool v0 = r0 < N_NODES;
    const bool v1 = r1 < N_NODES;
    const float* xr0 = x + (size_t)(v0 ? r0 : 0) * IN_CH;
    const float* xr1 = x + (size_t)(v1 ? r1 : 0) * IN_CH;

    float acc[8][4];
#pragma unroll
    for (int nt = 0; nt < 8; nt++)
#pragma unroll
        for (int i = 0; i < 4; i++) acc[nt][i] = 0.f;

    const int cn   = tid >> 1;
    const int part = tid & 1;

#pragma unroll
    for (int half = 0; half < 2; half++) {
        if (half) __syncthreads();
        {
            const uint4* srcH = (const uint4*)&g_Wh[half * 4096 + cn * 64 + part * 32];
            const uint4* srcL = (const uint4*)&g_Wl[half * 4096 + cn * 64 + part * 32];
            uint4* dstH = (uint4*)&sBh[cn][part * 32];
            uint4* dstL = (uint4*)&sBl[cn][part * 32];
#pragma unroll
            for (int i = 0; i < 8; i++) { dstH[i] = srcH[i]; dstL[i] = srcL[i]; }
        }
        __syncthreads();

#pragma unroll
        for (int kc = 0; kc < 8; kc++) {
            const int k0 = half * 128 + kc * 16 + tig * 2;
            float2 a0 = *(const float2*)(xr0 + k0);
            float2 a4 = *(const float2*)(xr0 + k0 + 8);
            float2 c0 = *(const float2*)(xr1 + k0);
            float2 c4 = *(const float2*)(xr1 + k0 + 8);
            uint32_t ah[4], al[4];
            ah[0] = pack_bf16(a0.x, a0.y);
            ah[1] = pack_bf16(c0.x, c0.y);
            ah[2] = pack_bf16(a4.x, a4.y);
            ah[3] = pack_bf16(c4.x, c4.y);
            al[0] = pack_bf16(a0.x - bf16lo_val(ah[0]), a0.y - bf16hi_val(ah[0]));
            al[1] = pack_bf16(c0.x - bf16lo_val(ah[1]), c0.y - bf16hi_val(ah[1]));
            al[2] = pack_bf16(a4.x - bf16lo_val(ah[2]), a4.y - bf16hi_val(ah[2]));
            al[3] = pack_bf16(c4.x - bf16lo_val(ah[3]), c4.y - bf16hi_val(ah[3]));
#pragma unroll
            for (int nt = 0; nt < 8; nt++) {
                const int n = nt * 8 + g;
                const int kw = kc * 8 + tig;
                uint32_t bh0 = sBh[n][kw], bh1 = sBh[n][kw + 4];
                uint32_t bl0 = sBl[n][kw], bl1 = sBl[n][kw + 4];
                mma_bf16(acc[nt], ah, bh0, bh1);
                mma_bf16(acc[nt], al, bh0, bh1);
                mma_bf16(acc[nt], ah, bl0, bl1);
            }
        }
    }

    // ---- epilogue: bias into acc, e0/e1 reduce, feature + self exp stores ----
    float e0a = 0.f, e1a = 0.f, e0b = 0.f, e1b = 0.f;
#pragma unroll
    for (int nt = 0; nt < 8; nt++) {
        int col = nt * 8 + tig * 2;
        float bi0 = __ldg(&b[col]);
        float bi1 = __ldg(&b[col + 1]);
        float at00 = __ldg(&att[col * 2 + 0]),   at01 = __ldg(&att[col * 2 + 1]);
        float at10 = __ldg(&att[(col + 1) * 2]), at11 = __ldg(&att[(col + 1) * 2 + 1]);
        acc[nt][0] += bi0; acc[nt][1] += bi1;
        acc[nt][2] += bi0; acc[nt][3] += bi1;
        e0a += acc[nt][0] * at00 + acc[nt][1] * at10;
        e1a += acc[nt][0] * at01 + acc[nt][1] * at11;
        e0b += acc[nt][2] * at00 + acc[nt][3] * at10;
        e1b += acc[nt][2] * at01 + acc[nt][3] * at11;
    }
#pragma unroll
    for (int o = 1; o <= 2; o <<= 1) {
        e0a += __shfl_xor_sync(0xffffffffu, e0a, o);
        e1a += __shfl_xor_sync(0xffffffffu, e1a, o);
        e0b += __shfl_xor_sync(0xffffffffu, e0b, o);
        e1b += __shfl_xor_sync(0xffffffffu, e1b, o);
    }
#pragma unroll
    for (int nt = 0; nt < 8; nt++) {
        int col = nt * 8 + tig * 2;
        if (v0) *(float2*)&g_feature[(size_t)r0 * OUT_CH + col] = make_float2(acc[nt][0], acc[nt][1]);
        if (v1) *(float2*)&g_feature[(size_t)r1 * OUT_CH + col] = make_float2(acc[nt][2], acc[nt][3]);
    }
    if (tig == 0) {
        if (v0) { g_e0[r0] = e0a; g_e1[r0] = e1a; g_es[r0] = __expf(lrelu(e0a + e1a)); }
        if (v1) { g_e0[r1] = e0b; g_e1[r1] = e1b; g_es[r1] = __expf(lrelu(e0b + e1b)); }
    }
}

// ------------- K2a: in-degree histogram ----------------------------------------
__global__ __launch_bounds__(256) void k_hist(const int* __restrict__ ei) {
    int e = blockIdx.x * 256 + threadIdx.x;
    if (e >= N_EDGES) return;
    atomicAdd(&g_cnt[__ldg(&ei[e])], 1);
}

// ------------- K2b: full-chip 3-stage scan -------------------------------------
// stage 1: per-block sums of 256 counts
__global__ __launch_bounds__(256) void k_scan1() {
    __shared__ int ws[8];
    const int t = threadIdx.x, lane = t & 31, w = t >> 5;
    const int i = blockIdx.x * 256 + t;
    int v = (i < N_NODES) ? g_cnt[i] : 0;
#pragma unroll
    for (int o = 16; o; o >>= 1) v += __shfl_xor_sync(0xffffffffu, v, o);
    if (lane == 0) ws[w] = v;
    __syncthreads();
    if (t == 0) {
        int s = 0;
#pragma unroll
        for (int j = 0; j < 8; j++) s += ws[j];
        g_bsum[blockIdx.x] = s;
    }
}
// stage 2: exclusive scan of 196 block sums (1 block)
__global__ __launch_bounds__(256) void k_scan2() {
    __shared__ int ws[8];
    const int t = threadIdx.x, lane = t & 31, w = t >> 5;
    int v = (t < NB_SCAN) ? g_bsum[t] : 0;
    int inc = v;
#pragma unroll
    for (int o = 1; o < 32; o <<= 1) {
        int u = __shfl_up_sync(0xffffffffu, inc, o);
        if (lane >= o) inc += u;
    }
    if (lane == 31) ws[w] = inc;
    __syncthreads();
    if (w == 0) {
        int s = (lane < 8) ? ws[lane] : 0;
#pragma unroll
        for (int o = 1; o < 8; o <<= 1) {
            int u = __shfl_up_sync(0xffffffffu, s, o);
            if (lane >= o) s += u;
        }
        if (lane < 8) ws[lane] = s;
    }
    __syncthreads();
    int excl = (w ? ws[w - 1] : 0) + inc - v;
    if (t < NB_SCAN) g_boff[t] = excl;
    if (t == 0) g_rowptr[N_NODES] = N_EDGES;
}
// stage 3: block-level exclusive scan + block offset -> rowptr, cursor
__global__ __launch_bounds__(256) void k_scan3() {
    __shared__ int ws[8];
    const int t = threadIdx.x, lane = t & 31, w = t >> 5;
    const int i = blockIdx.x * 256 + t;
    int c = (i < N_NODES) ? g_cnt[i] : 0;
    int inc = c;
#pragma unroll
    for (int o = 1; o < 32; o <<= 1) {
        int u = __shfl_up_sync(0xffffffffu, inc, o);
        if (lane >= o) inc += u;
    }
    if (lane == 31) ws[w] = inc;
    __syncthreads();
    if (w == 0) {
        int s = (lane < 8) ? ws[lane] : 0;
#pragma unroll
        for (int o = 1; o < 8; o <<= 1) {
            int u = __shfl_up_sync(0xffffffffu, s, o);
            if (lane >= o) s += u;
        }
        if (lane < 8) ws[lane] = s;
    }
    __syncthreads();
    int pos = g_boff[blockIdx.x] + (w ? ws[w - 1] : 0) + inc - c;
    if (i < N_NODES) {
        g_rowptr[i] = pos;
        g_cursor[i] = pos;
    }
}

// ------------- K2c: scatter src indices into CSR slots -------------------------
__global__ __launch_bounds__(256) void k_scatter(const int* __restrict__ ei) {
    int e = blockIdx.x * 256 + threadIdx.x;
    if (e >= N_EDGES) return;
    int tar = __ldg(&ei[e]);
    int src = __ldg(&ei[N_EDGES + e]);
    int pos = atomicAdd(&g_cursor[tar], 1);
    g_csrc[pos] = src;
}

// ------------- K3: pull-mode aggregation (warp per node, register acc) ---------
__global__ __launch_bounds__(256) void k_agg(float* __restrict__ out) {
    const int warp = (blockIdx.x * 256 + threadIdx.x) >> 5;
    const int lane = threadIdx.x & 31;
    if (warp >= N_NODES) return;
    const int n = warp;
    const int beg = g_rowptr[n];
    const int end = g_rowptr[n + 1];
    const float e0n = g_e0[n];
    const float es  = g_es[n];
    float2 fs = *(const float2*)&g_feature[(size_t)n * OUT_CH + lane * 2];
    float acc0 = es * fs.x, acc1 = es * fs.y, dsum = es;

    for (int j0 = beg; j0 < end; j0 += 32) {
        const int idx = j0 + lane;
        int src = 0;
        float ee = 0.f;
        if (idx < end) {
            src = __ldg(&g_csrc[idx]);
            ee  = __expf(lrelu(e0n + __ldg(&g_e1[src])));
        }
        const int cnt = min(32, end - j0);
        for (int j = 0; j < cnt; j++) {
            int   s = __shfl_sync(0xffffffffu, src, j);
            float w = __shfl_sync(0xffffffffu, ee,  j);
            float2 f = *(const float2*)&g_feature[(size_t)s * OUT_CH + lane * 2];
            acc0 += w * f.x;
            acc1 += w * f.y;
            dsum += w;
        }
    }
    const float rd = 1.0f / dsum;
    *(float2*)&out[(size_t)n * OUT_CH + lane * 2] = make_float2(acc0 * rd, acc1 * rd);
}

// -------------------------------------------------------------------------------
extern "C" void kernel_launch(void* const* d_in, const int* in_sizes, int n_in,
                              void* d_out, int out_size) {
    const float* x   = (const float*)d_in[0];
    const int*   ei  = (const int*)d_in[1];   // int32 (JAX x64 disabled)
    const float* W   = (const float*)d_in[2];
    const float* b   = (const float*)d_in[3];
    const float* att = (const float*)d_in[4];
    float* out = (float*)d_out;

    // K0: W -> bf16 hi/lo + histogram zero
    k_wconv<<<32, 256>>>(W);
    // K2a: in-degree histogram
    k_hist<<<(N_EDGES + 255) / 256, 256>>>(ei);
    // K1: HMMA projection + attention pre-terms
    k_gemm_tc<<<(N_NODES + 63) / 64, 128>>>(x, b, att);
    // K2b: full-chip 3-stage scan -> rowptr/cursors
    k_scan1<<<NB_SCAN, 256>>>();
    k_scan2<<<1, 256>>>();
    k_scan3<<<NB_SCAN, 256>>>();
    // K2c: scatter src ids
    k_scatter<<<(N_EDGES + 255) / 256, 256>>>(ei);
    // K3: pull aggregation + in-register softmax denominator
    k_agg<<<(N_NODES * 32 + 255) / 256, 256>>>(out);
}

// round 10
// speedup vs baseline: 1.9182x; 1.0451x over previous
#include <cuda_runtime.h>
#include <cuda_bf16.h>
#include <cstdint>

#define N_NODES 50000
#define N_EDGES 800000
#define IN_CH   256
#define OUT_CH  64
#define NEG_SLOPE 0.2f
#define NB_SCAN 196   // ceil(N_NODES/256)

// dynamic smem: sBh[64][68] | sBl[64][68] | xs[2][128][36] floats
#define SB_WORDS   (64 * 68)
#define XS_FLOATS  (2 * 128 * 36)
#define DYN_BYTES  ((2 * SB_WORDS + XS_FLOATS) * 4)   // 71680

// ---------------- scratch (device globals; no allocations allowed) -------------
__device__ float    g_feature[N_NODES * OUT_CH];
__device__ float    g_e0[N_NODES];
__device__ float    g_e1[N_NODES];
__device__ float    g_es[N_NODES];          // exp(self logit)
__device__ uint32_t g_Wh[2 * 64 * 64];      // [half][n][kw] bf16x2 hi
__device__ uint32_t g_Wl[2 * 64 * 64];      // [half][n][kw] bf16x2 lo
__device__ int      g_cnt[N_NODES];
__device__ int      g_rowptr[N_NODES + 1];
__device__ int      g_cursor[N_NODES];
__device__ int      g_csrc[N_EDGES];
__device__ int      g_bsum[NB_SCAN];

__device__ __forceinline__ float lrelu(float v) {
    return v > 0.0f ? v : NEG_SLOPE * v;
}
__device__ __forceinline__ uint32_t smem_u32(const void* p) {
    uint32_t a;
    asm("{ .reg .u64 t; cvta.to.shared.u64 t, %1; cvt.u32.u64 %0, t; }" : "=r"(a) : "l"(p));
    return a;
}
__device__ __forceinline__ void cp16(void* dst, const void* src) {
    asm volatile("cp.async.cg.shared.global [%0], [%1], 16;"
                 :: "r"(smem_u32(dst)), "l"(src) : "memory");
}
#define CP_COMMIT() asm volatile("cp.async.commit_group;" ::: "memory")
#define CP_WAIT(n)  asm volatile("cp.async.wait_group %0;" :: "n"(n) : "memory")

// pack two floats (even, odd) into bf16x2 (even in low half)
__device__ __forceinline__ uint32_t pack_bf16(float e, float o) {
    uint32_t d;
    asm("cvt.rn.bf16x2.f32 %0, %1, %2;" : "=r"(d) : "f"(o), "f"(e));
    return d;
}
__device__ __forceinline__ float bf16lo_val(uint32_t w) { return __uint_as_float(w << 16); }
__device__ __forceinline__ float bf16hi_val(uint32_t w) { return __uint_as_float(w & 0xFFFF0000u); }

// m16n8k16 row.col bf16 HMMA (target-generic; tcgen05 unavailable on this build)
__device__ __forceinline__ void mma_bf16(float* c, const uint32_t* a, uint32_t b0, uint32_t b1) {
    asm volatile(
        "mma.sync.aligned.m16n8k16.row.col.f32.bf16.bf16.f32 "
        "{%0,%1,%2,%3}, {%4,%5,%6,%7}, {%8,%9}, {%0,%1,%2,%3};"
        : "+f"(c[0]), "+f"(c[1]), "+f"(c[2]), "+f"(c[3])
        : "r"(a[0]), "r"(a[1]), "r"(a[2]), "r"(a[3]), "r"(b0), "r"(b1));
}

// ------------- K0: one-time W -> bf16 hi/lo conversion + histogram zero --------
__global__ __launch_bounds__(256) void k_wconv(const float* __restrict__ W) {
    int idx = blockIdx.x * 256 + threadIdx.x;    // 0..8191
    int half = idx >> 12, rem = idx & 4095;
    int n = rem >> 6, j = rem & 63;
    int k = half * 128 + j * 2;
    float w0 = W[n * 256 + k], w1 = W[n * 256 + k + 1];
    uint32_t h = pack_bf16(w0, w1);
    uint32_t l = pack_bf16(w0 - bf16lo_val(h), w1 - bf16hi_val(h));
    g_Wh[idx] = h;
    g_Wl[idx] = l;
    for (int i = idx; i < N_NODES; i += 8192) g_cnt[i] = 0;
}

// ------------- K1: HMMA projection, cp.async-pipelined x staging ---------------
// 256 threads = 8 warps; warp w -> rows [blk*128 + w*16, +16). K in 8 chunks of
// 32 floats, double-buffered in smem via LDGSTS. B (W bf16 hi/lo) in smem per
// K-half, refilled once at chunk 4.
__global__ __launch_bounds__(256, 3) void k_gemm_tc(const float* __restrict__ x,
                                                    const float* __restrict__ b,
                                                    const float* __restrict__ att) {
    extern __shared__ __align__(16) uint32_t dyn[];
    uint32_t (*sBh)[68] = (uint32_t(*)[68])dyn;
    uint32_t (*sBl)[68] = (uint32_t(*)[68])(dyn + SB_WORDS);
    float    (*xs)[128][36] = (float(*)[128][36])(dyn + 2 * SB_WORDS);

    const int tid  = threadIdx.x;
    const int wid  = tid >> 5;
    const int lane = tid & 31;
    const int g    = lane >> 2;
    const int tig  = lane & 3;

    const int base = blockIdx.x * 128 + wid * 16;
    const int r0 = base + g;
    const int r1 = base + g + 8;
    const bool v0 = r0 < N_NODES;
    const bool v1 = r1 < N_NODES;

    // cp.async source row (clamped; garbage rows never stored)
    const int rl      = tid >> 1;                  // local row 0..127
    const int half16  = (tid & 1) * 16;            // float offset in 32-chunk
    const int gr      = min(blockIdx.x * 128 + rl, N_NODES - 1);
    const float* xsrc = x + (size_t)gr * IN_CH + half16;

    float acc[8][4];
#pragma unroll
    for (int nt = 0; nt < 8; nt++)
#pragma unroll
        for (int i = 0; i < 4; i++) acc[nt][i] = 0.f;

    // fill B half h
    auto fillB = [&](int h) {
        const int cn = tid >> 2, part = (tid & 3) * 16;
        const uint4* sH = (const uint4*)&g_Wh[h * 4096 + cn * 64 + part];
        const uint4* sL = (const uint4*)&g_Wl[h * 4096 + cn * 64 + part];
        uint4* dH = (uint4*)&sBh[cn][part];
        uint4* dL = (uint4*)&sBl[cn][part];
#pragma unroll
        for (int i = 0; i < 4; i++) { dH[i] = sH[i]; dL[i] = sL[i]; }
    };
    auto issue = [&](int c) {
        float* dst = &xs[c & 1][rl][half16];
        const float* src = xsrc + c * 32;
#pragma unroll
        for (int i = 0; i < 4; i++) cp16(dst + i * 4, src + i * 4);
        CP_COMMIT();
    };

    issue(0);
    fillB(0);
    __syncthreads();                       // B half0 visible

    for (int c = 0; c < 8; c++) {
        if (c < 7) issue(c + 1);
        if (c < 7) { CP_WAIT(1); } else { CP_WAIT(0); }
        __syncthreads();                   // chunk c staged for all
        if (c == 4) { fillB(1); __syncthreads(); }

        const int buf = c & 1;
        const int kh  = (c & 3) * 2;       // kc-within-half base (2 kc per chunk)
#pragma unroll
        for (int kk = 0; kk < 2; kk++) {
            const int kloc = kk * 16 + tig * 2;
            float2 a0 = *(const float2*)&xs[buf][wid * 16 + g][kloc];
            float2 a4 = *(const float2*)&xs[buf][wid * 16 + g][kloc + 8];
            float2 c0 = *(const float2*)&xs[buf][wid * 16 + g + 8][kloc];
            float2 c4 = *(const float2*)&xs[buf][wid * 16 + g + 8][kloc + 8];
            uint32_t ah[4], al[4];
            ah[0] = pack_bf16(a0.x, a0.y);
            ah[1] = pack_bf16(c0.x, c0.y);
            ah[2] = pack_bf16(a4.x, a4.y);
            ah[3] = pack_bf16(c4.x, c4.y);
            al[0] = pack_bf16(a0.x - bf16lo_val(ah[0]), a0.y - bf16hi_val(ah[0]));
            al[1] = pack_bf16(c0.x - bf16lo_val(ah[1]), c0.y - bf16hi_val(ah[1]));
            al[2] = pack_bf16(a4.x - bf16lo_val(ah[2]), a4.y - bf16hi_val(ah[2]));
            al[3] = pack_bf16(c4.x - bf16lo_val(ah[3]), c4.y - bf16hi_val(ah[3]));
            const int kw = (kh + kk) * 8 + tig;
#pragma unroll
            for (int nt = 0; nt < 8; nt++) {
                const int n = nt * 8 + g;
                uint32_t bh0 = sBh[n][kw], bh1 = sBh[n][kw + 4];
                uint32_t bl0 = sBl[n][kw], bl1 = sBl[n][kw + 4];
                mma_bf16(acc[nt], ah, bh0, bh1);
                mma_bf16(acc[nt], al, bh0, bh1);
                mma_bf16(acc[nt], ah, bl0, bl1);
            }
        }
        __syncthreads();                   // done reading buf before re-issue
    }

    // ---- epilogue: bias, e0/e1 reduce, feature + self-exp stores ----
    float e0a = 0.f, e1a = 0.f, e0b = 0.f, e1b = 0.f;
#pragma unroll
    for (int nt = 0; nt < 8; nt++) {
        int col = nt * 8 + tig * 2;
        float bi0 = __ldg(&b[col]);
        float bi1 = __ldg(&b[col + 1]);
        float at00 = __ldg(&att[col * 2 + 0]),   at01 = __ldg(&att[col * 2 + 1]);
        float at10 = __ldg(&att[(col + 1) * 2]), at11 = __ldg(&att[(col + 1) * 2 + 1]);
        acc[nt][0] += bi0; acc[nt][1] += bi1;
        acc[nt][2] += bi0; acc[nt][3] += bi1;
        e0a += acc[nt][0] * at00 + acc[nt][1] * at10;
        e1a += acc[nt][0] * at01 + acc[nt][1] * at11;
        e0b += acc[nt][2] * at00 + acc[nt][3] * at10;
        e1b += acc[nt][2] * at01 + acc[nt][3] * at11;
    }
#pragma unroll
    for (int o = 1; o <= 2; o <<= 1) {
        e0a += __shfl_xor_sync(0xffffffffu, e0a, o);
        e1a += __shfl_xor_sync(0xffffffffu, e1a, o);
        e0b += __shfl_xor_sync(0xffffffffu, e0b, o);
        e1b += __shfl_xor_sync(0xffffffffu, e1b, o);
    }
#pragma unroll
    for (int nt = 0; nt < 8; nt++) {
        int col = nt * 8 + tig * 2;
        if (v0) *(float2*)&g_feature[(size_t)r0 * OUT_CH + col] = make_float2(acc[nt][0], acc[nt][1]);
        if (v1) *(float2*)&g_feature[(size_t)r1 * OUT_CH + col] = make_float2(acc[nt][2], acc[nt][3]);
    }
    if (tig == 0) {
        if (v0) { g_e0[r0] = e0a; g_e1[r0] = e1a; g_es[r0] = __expf(lrelu(e0a + e1a)); }
        if (v1) { g_e0[r1] = e0b; g_e1[r1] = e1b; g_es[r1] = __expf(lrelu(e0b + e1b)); }
    }
}

// ------------- K2a: in-degree histogram ----------------------------------------
__global__ __launch_bounds__(256) void k_hist(const int* __restrict__ ei) {
    int e = blockIdx.x * 256 + threadIdx.x;
    if (e >= N_EDGES) return;
    atomicAdd(&g_cnt[__ldg(&ei[e])], 1);
}

// ------------- K2b1: per-block sums --------------------------------------------
__global__ __launch_bounds__(256) void k_scan1() {
    __shared__ int ws[8];
    const int t = threadIdx.x, lane = t & 31, w = t >> 5;
    const int i = blockIdx.x * 256 + t;
    int v = (i < N_NODES) ? g_cnt[i] : 0;
#pragma unroll
    for (int o = 16; o; o >>= 1) v += __shfl_xor_sync(0xffffffffu, v, o);
    if (lane == 0) ws[w] = v;
    __syncthreads();
    if (t == 0) {
        int s = 0;
#pragma unroll
        for (int j = 0; j < 8; j++) s += ws[j];
        g_bsum[blockIdx.x] = s;
    }
}

// ------------- K2b2: fused block-offset + local scan -> rowptr, cursor ---------
// Each block redundantly reduces bsum[j<bid] (196 L2-hot ints), then does its
// local exclusive scan.
__global__ __launch_bounds__(256) void k_scan23() {
    __shared__ int ws[8];
    __shared__ int sboff;
    const int t = threadIdx.x, lane = t & 31, w = t >> 5;

    // block offset = sum of bsum[j] for j < bid
    int v = (t < NB_SCAN && t < blockIdx.x) ? g_bsum[t] : 0;
#pragma unroll
    for (int o = 16; o; o >>= 1) v += __shfl_xor_sync(0xffffffffu, v, o);
    if (lane == 0) ws[w] = v;
    __syncthreads();
    if (t == 0) {
        int s = 0;
#pragma unroll
        for (int j = 0; j < 8; j++) s += ws[j];
        sboff = s;
    }
    __syncthreads();
    const int boff = sboff;
    __syncthreads();   // ws reuse below

    // local exclusive scan of counts
    const int i = blockIdx.x * 256 + t;
    int c = (i < N_NODES) ? g_cnt[i] : 0;
    int inc = c;
#pragma unroll
    for (int o = 1; o < 32; o <<= 1) {
        int u = __shfl_up_sync(0xffffffffu, inc, o);
        if (lane >= o) inc += u;
    }
    if (lane == 31) ws[w] = inc;
    __syncthreads();
    if (w == 0) {
        int s = (lane < 8) ? ws[lane] : 0;
#pragma unroll
        for (int o = 1; o < 8; o <<= 1) {
            int u = __shfl_up_sync(0xffffffffu, s, o);
            if (lane >= o) s += u;
        }
        if (lane < 8) ws[lane] = s;
    }
    __syncthreads();
    int pos = boff + (w ? ws[w - 1] : 0) + inc - c;
    if (i < N_NODES) {
        g_rowptr[i] = pos;
        g_cursor[i] = pos;
    }
    if (blockIdx.x == 0 && t == 0) g_rowptr[N_NODES] = N_EDGES;
}

// ------------- K2c: scatter src indices into CSR slots -------------------------
__global__ __launch_bounds__(256) void k_scatter(const int* __restrict__ ei) {
    int e = blockIdx.x * 256 + threadIdx.x;
    if (e >= N_EDGES) return;
    int tar = __ldg(&ei[e]);
    int src = __ldg(&ei[N_EDGES + e]);
    int pos = atomicAdd(&g_cursor[tar], 1);
    g_csrc[pos] = src;
}

// ------------- K3: pull-mode aggregation (warp per node, register acc) ---------
__global__ __launch_bounds__(256) void k_agg(float* __restrict__ out) {
    const int warp = (blockIdx.x * 256 + threadIdx.x) >> 5;
    const int lane = threadIdx.x & 31;
    if (warp >= N_NODES) return;
    const int n = warp;
    const int beg = g_rowptr[n];
    const int end = g_rowptr[n + 1];
    const float e0n = g_e0[n];
    const float es  = g_es[n];
    float2 fs = *(const float2*)&g_feature[(size_t)n * OUT_CH + lane * 2];
    float acc0 = es * fs.x, acc1 = es * fs.y, dsum = es;

    for (int j0 = beg; j0 < end; j0 += 32) {
        const int idx = j0 + lane;
        int src = 0;
        float ee = 0.f;
        if (idx < end) {
            src = __ldg(&g_csrc[idx]);
            ee  = __expf(lrelu(e0n + __ldg(&g_e1[src])));
        }
        const int cnt = min(32, end - j0);
        for (int j = 0; j < cnt; j++) {
            int   s = __shfl_sync(0xffffffffu, src, j);
            float w = __shfl_sync(0xffffffffu, ee,  j);
            float2 f = *(const float2*)&g_feature[(size_t)s * OUT_CH + lane * 2];
            acc0 += w * f.x;
            acc1 += w * f.y;
            dsum += w;
        }
    }
    const float rd = 1.0f / dsum;
    *(float2*)&out[(size_t)n * OUT_CH + lane * 2] = make_float2(acc0 * rd, acc1 * rd);
}

// -------------------------------------------------------------------------------
extern "C" void kernel_launch(void* const* d_in, const int* in_sizes, int n_in,
                              void* d_out, int out_size) {
    const float* x   = (const float*)d_in[0];
    const int*   ei  = (const int*)d_in[1];   // int32 (JAX x64 disabled)
    const float* W   = (const float*)d_in[2];
    const float* b   = (const float*)d_in[3];
    const float* att = (const float*)d_in[4];
    float* out = (float*)d_out;

    cudaFuncSetAttribute(k_gemm_tc, cudaFuncAttributeMaxDynamicSharedMemorySize, DYN_BYTES);

    // 1: W -> bf16 hi/lo + histogram zero
    k_wconv<<<32, 256>>>(W);
    // 2: in-degree histogram
    k_hist<<<(N_EDGES + 255) / 256, 256>>>(ei);
    // 3: per-block count sums
    k_scan1<<<NB_SCAN, 256>>>();
    // 4: HMMA projection (4th launch -> lands in the ncu window next round)
    k_gemm_tc<<<(N_NODES + 127) / 128, 256, DYN_BYTES>>>(x, b, att);
    // 5: block offsets + local scan -> rowptr/cursor
    k_scan23<<<NB_SCAN, 256>>>();
    // 6: scatter src ids
    k_scatter<<<(N_EDGES + 255) / 256, 256>>>(ei);
    // 7: pull aggregation + in-register softmax denominator
    k_agg<<<(N_NODES * 32 + 255) / 256, 256>>>(out);
}

// round 11
// speedup vs baseline: 2.0551x; 1.0713x over previous
#include <cuda_runtime.h>
#include <cuda_bf16.h>
#include <cstdint>

#define N_NODES 50000
#define N_EDGES 800000
#define IN_CH   256
#define OUT_CH  64
#define NEG_SLOPE 0.2f
#define NB_SCAN 196   // ceil(N_NODES/256)

// dynamic smem: sB4[64][36] uint4 (interleaved bh/bl quads, padded) | xs[2][128][36] floats
#define SB_UINT4   (64 * 36)                      // 2304 uint4 = 36864 B
#define XS_FLOATS  (2 * 128 * 36)                 // 36864 B
#define DYN_BYTES  (SB_UINT4 * 16 + XS_FLOATS * 4)   // 73728

// ---------------- scratch (device globals; no allocations allowed) -------------
__device__ float    g_feature[N_NODES * OUT_CH];
__device__ float    g_e0[N_NODES];
__device__ float    g_e1[N_NODES];
__device__ float    g_es[N_NODES];              // exp(self logit)
__device__ uint4    g_Wi[2 * 64 * 32];          // [half][n][kc*4+tig] = {bh0,bh1,bl0,bl1}
__device__ int      g_cnt[N_NODES];
__device__ int      g_rowptr[N_NODES + 1];
__device__ int      g_cursor[N_NODES];
__device__ int      g_csrc[N_EDGES];
__device__ int      g_bsum[NB_SCAN];

__device__ __forceinline__ float lrelu(float v) {
    return v > 0.0f ? v : NEG_SLOPE * v;
}
__device__ __forceinline__ uint32_t smem_u32(const void* p) {
    uint32_t a;
    asm("{ .reg .u64 t; cvta.to.shared.u64 t, %1; cvt.u32.u64 %0, t; }" : "=r"(a) : "l"(p));
    return a;
}
__device__ __forceinline__ void cp16(void* dst, const void* src) {
    asm volatile("cp.async.cg.shared.global [%0], [%1], 16;"
                 :: "r"(smem_u32(dst)), "l"(src) : "memory");
}
#define CP_COMMIT() asm volatile("cp.async.commit_group;" ::: "memory")
#define CP_WAIT(n)  asm volatile("cp.async.wait_group %0;" :: "n"(n) : "memory")

// pack two floats (even, odd) into bf16x2 (even in low half)
__device__ __forceinline__ uint32_t pack_bf16(float e, float o) {
    uint32_t d;
    asm("cvt.rn.bf16x2.f32 %0, %1, %2;" : "=r"(d) : "f"(o), "f"(e));
    return d;
}
__device__ __forceinline__ float bf16lo_val(uint32_t w) { return __uint_as_float(w << 16); }
__device__ __forceinline__ float bf16hi_val(uint32_t w) { return __uint_as_float(w & 0xFFFF0000u); }

// m16n8k16 row.col bf16 HMMA (target-generic; tcgen05 unavailable on this build)
__device__ __forceinline__ void mma_bf16(float* c, const uint32_t* a, uint32_t b0, uint32_t b1) {
    asm volatile(
        "mma.sync.aligned.m16n8k16.row.col.f32.bf16.bf16.f32 "
        "{%0,%1,%2,%3}, {%4,%5,%6,%7}, {%8,%9}, {%0,%1,%2,%3};"
        : "+f"(c[0]), "+f"(c[1]), "+f"(c[2]), "+f"(c[3])
        : "r"(a[0]), "r"(a[1]), "r"(a[2]), "r"(a[3]), "r"(b0), "r"(b1));
}

// ------------- K0a: W -> interleaved bf16 hi/lo quads --------------------------
// Thread idx = (half, n, kc, tig). Quad = {Wh[kw], Wh[kw+4], Wl[kw], Wl[kw+4]},
// kw = kc*8 + tig; word j covers floats k = half*128 + 2j.
__global__ __launch_bounds__(256) void k_wconv(const float* __restrict__ W) {
    int idx = blockIdx.x * 256 + threadIdx.x;    // 0..4095
    int half = idx >> 11, rem = idx & 2047;
    int n = rem >> 5, m = rem & 31;
    int kc = m >> 2, tig = m & 3;
    int kw = kc * 8 + tig;
    int k1 = half * 128 + 2 * kw;
    int k2 = k1 + 8;                              // 2*(kw+4)
    float a0 = W[n * 256 + k1], a1 = W[n * 256 + k1 + 1];
    float b0 = W[n * 256 + k2], b1 = W[n * 256 + k2 + 1];
    uint32_t h1 = pack_bf16(a0, a1);
    uint32_t h2 = pack_bf16(b0, b1);
    uint32_t l1 = pack_bf16(a0 - bf16lo_val(h1), a1 - bf16hi_val(h1));
    uint32_t l2 = pack_bf16(b0 - bf16lo_val(h2), b1 - bf16hi_val(h2));
    g_Wi[half * 2048 + n * 32 + m] = make_uint4(h1, h2, l1, l2);
}

// ------------- K0b: zero in-degree histogram (head of the edge chain) ----------
__global__ __launch_bounds__(256) void k_zero() {
    int i = blockIdx.x * 256 + threadIdx.x;
    if (i < N_NODES) g_cnt[i] = 0;
}

// ------------- K1: HMMA projection, cp.async x staging + LDS.128 B fetch -------
__global__ __launch_bounds__(256, 3) void k_gemm_tc(const float* __restrict__ x,
                                                    const float* __restrict__ b,
                                                    const float* __restrict__ att) {
    extern __shared__ __align__(16) uint4 dyn4[];
    uint4* sB4 = dyn4;                                 // [n*36 + kc*4 + tig]
    float* xsf = (float*)(dyn4 + SB_UINT4);            // [buf*128*36 + row*36 + k]

    const int tid  = threadIdx.x;
    const int wid  = tid >> 5;
    const int lane = tid & 31;
    const int g    = lane >> 2;
    const int tig  = lane & 3;

    const int base = blockIdx.x * 128 + wid * 16;
    const int r0 = base + g;
    const int r1 = base + g + 8;
    const bool v0 = r0 < N_NODES;
    const bool v1 = r1 < N_NODES;

    const int rl      = tid >> 1;                  // local row 0..127
    const int half16  = (tid & 1) * 16;
    const int gr      = min(blockIdx.x * 128 + rl, N_NODES - 1);
    const float* xsrc = x + (size_t)gr * IN_CH + half16;

    float acc[8][4];
#pragma unroll
    for (int nt = 0; nt < 8; nt++)
#pragma unroll
        for (int i = 0; i < 4; i++) acc[nt][i] = 0.f;

    auto fillB = [&](int h) {
#pragma unroll
        for (int i = 0; i < 8; i++) {
            int s = tid * 8 + i;                   // 0..2047
            sB4[(s >> 5) * 36 + (s & 31)] = g_Wi[h * 2048 + s];
        }
    };
    auto issue = [&](int c) {
        float* dst = &xsf[(c & 1) * (128 * 36) + rl * 36 + half16];
        const float* src = xsrc + c * 32;
#pragma unroll
        for (int i = 0; i < 4; i++) cp16(dst + i * 4, src + i * 4);
        CP_COMMIT();
    };

    issue(0);
    fillB(0);
    __syncthreads();

    for (int c = 0; c < 8; c++) {
        if (c < 7) issue(c + 1);
        if (c < 7) { CP_WAIT(1); } else { CP_WAIT(0); }
        __syncthreads();
        if (c == 4) { fillB(1); __syncthreads(); }

        const float* xb = xsf + (c & 1) * (128 * 36);
        const int kh = (c & 3) * 2;
#pragma unroll
        for (int kk = 0; kk < 2; kk++) {
            const int kloc = kk * 16 + tig * 2;
            const float* row0 = xb + (wid * 16 + g) * 36;
            const float* row1 = xb + (wid * 16 + g + 8) * 36;
            float2 a0 = *(const float2*)(row0 + kloc);
            float2 a4 = *(const float2*)(row0 + kloc + 8);
            float2 c0 = *(const float2*)(row1 + kloc);
            float2 c4 = *(const float2*)(row1 + kloc + 8);
            uint32_t ah[4], al[4];
            ah[0] = pack_bf16(a0.x, a0.y);
            ah[1] = pack_bf16(c0.x, c0.y);
            ah[2] = pack_bf16(a4.x, a4.y);
            ah[3] = pack_bf16(c4.x, c4.y);
            al[0] = pack_bf16(a0.x - bf16lo_val(ah[0]), a0.y - bf16hi_val(ah[0]));
            al[1] = pack_bf16(c0.x - bf16lo_val(ah[1]), c0.y - bf16hi_val(ah[1]));
            al[2] = pack_bf16(a4.x - bf16lo_val(ah[2]), a4.y - bf16hi_val(ah[2]));
            al[3] = pack_bf16(c4.x - bf16lo_val(ah[3]), c4.y - bf16hi_val(ah[3]));
            const int kq = (kh + kk) * 4 + tig;    // quad index within row
#pragma unroll
            for (int nt = 0; nt < 8; nt++) {
                uint4 B = sB4[(nt * 8 + g) * 36 + kq];   // one LDS.128
                mma_bf16(acc[nt], ah, B.x, B.y);
                mma_bf16(acc[nt], al, B.x, B.y);
                mma_bf16(acc[nt], ah, B.z, B.w);
            }
        }
        __syncthreads();
    }

    // ---- epilogue: bias, e0/e1 reduce, feature + self-exp stores ----
    float e0a = 0.f, e1a = 0.f, e0b = 0.f, e1b = 0.f;
#pragma unroll
    for (int nt = 0; nt < 8; nt++) {
        int col = nt * 8 + tig * 2;
        float bi0 = __ldg(&b[col]);
        float bi1 = __ldg(&b[col + 1]);
        float at00 = __ldg(&att[col * 2 + 0]),   at01 = __ldg(&att[col * 2 + 1]);
        float at10 = __ldg(&att[(col + 1) * 2]), at11 = __ldg(&att[(col + 1) * 2 + 1]);
        acc[nt][0] += bi0; acc[nt][1] += bi1;
        acc[nt][2] += bi0; acc[nt][3] += bi1;
        e0a += acc[nt][0] * at00 + acc[nt][1] * at10;
        e1a += acc[nt][0] * at01 + acc[nt][1] * at11;
        e0b += acc[nt][2] * at00 + acc[nt][3] * at10;
        e1b += acc[nt][2] * at01 + acc[nt][3] * at11;
    }
#pragma unroll
    for (int o = 1; o <= 2; o <<= 1) {
        e0a += __shfl_xor_sync(0xffffffffu, e0a, o);
        e1a += __shfl_xor_sync(0xffffffffu, e1a, o);
        e0b += __shfl_xor_sync(0xffffffffu, e0b, o);
        e1b += __shfl_xor_sync(0xffffffffu, e1b, o);
    }
#pragma unroll
    for (int nt = 0; nt < 8; nt++) {
        int col = nt * 8 + tig * 2;
        if (v0) *(float2*)&g_feature[(size_t)r0 * OUT_CH + col] = make_float2(acc[nt][0], acc[nt][1]);
        if (v1) *(float2*)&g_feature[(size_t)r1 * OUT_CH + col] = make_float2(acc[nt][2], acc[nt][3]);
    }
    if (tig == 0) {
        if (v0) { g_e0[r0] = e0a; g_e1[r0] = e1a; g_es[r0] = __expf(lrelu(e0a + e1a)); }
        if (v1) { g_e0[r1] = e0b; g_e1[r1] = e1b; g_es[r1] = __expf(lrelu(e0b + e1b)); }
    }
}

// ------------- K2a: in-degree histogram ----------------------------------------
__global__ __launch_bounds__(256) void k_hist(const int* __restrict__ ei) {
    int e = blockIdx.x * 256 + threadIdx.x;
    if (e >= N_EDGES) return;
    atomicAdd(&g_cnt[__ldg(&ei[e])], 1);
}

// ------------- K2b1: per-block sums --------------------------------------------
__global__ __launch_bounds__(256) void k_scan1() {
    __shared__ int ws[8];
    const int t = threadIdx.x, lane = t & 31, w = t >> 5;
    const int i = blockIdx.x * 256 + t;
    int v = (i < N_NODES) ? g_cnt[i] : 0;
#pragma unroll
    for (int o = 16; o; o >>= 1) v += __shfl_xor_sync(0xffffffffu, v, o);
    if (lane == 0) ws[w] = v;
    __syncthreads();
    if (t == 0) {
        int s = 0;
#pragma unroll
        for (int j = 0; j < 8; j++) s += ws[j];
        g_bsum[blockIdx.x] = s;
    }
}

// ------------- K2b2: fused block-offset + local scan -> rowptr, cursor ---------
__global__ __launch_bounds__(256) void k_scan23() {
    __shared__ int ws[8];
    __shared__ int sboff;
    const int t = threadIdx.x, lane = t & 31, w = t >> 5;

    int v = (t < NB_SCAN && t < blockIdx.x) ? g_bsum[t] : 0;
#pragma unroll
    for (int o = 16; o; o >>= 1) v += __shfl_xor_sync(0xffffffffu, v, o);
    if (lane == 0) ws[w] = v;
    __syncthreads();
    if (t == 0) {
        int s = 0;
#pragma unroll
        for (int j = 0; j < 8; j++) s += ws[j];
        sboff = s;
    }
    __syncthreads();
    const int boff = sboff;
    __syncthreads();

    const int i = blockIdx.x * 256 + t;
    int c = (i < N_NODES) ? g_cnt[i] : 0;
    int inc = c;
#pragma unroll
    for (int o = 1; o < 32; o <<= 1) {
        int u = __shfl_up_sync(0xffffffffu, inc, o);
        if (lane >= o) inc += u;
    }
    if (lane == 31) ws[w] = inc;
    __syncthreads();
    if (w == 0) {
        int s = (lane < 8) ? ws[lane] : 0;
#pragma unroll
        for (int o = 1; o < 8; o <<= 1) {
            int u = __shfl_up_sync(0xffffffffu, s, o);
            if (lane >= o) s += u;
        }
        if (lane < 8) ws[lane] = s;
    }
    __syncthreads();
    int pos = boff + (w ? ws[w - 1] : 0) + inc - c;
    if (i < N_NODES) {
        g_rowptr[i] = pos;
        g_cursor[i] = pos;
    }
    if (blockIdx.x == 0 && t == 0) g_rowptr[N_NODES] = N_EDGES;
}

// ------------- K2c: scatter src indices into CSR slots -------------------------
__global__ __launch_bounds__(256) void k_scatter(const int* __restrict__ ei) {
    int e = blockIdx.x * 256 + threadIdx.x;
    if (e >= N_EDGES) return;
    int tar = __ldg(&ei[e]);
    int src = __ldg(&ei[N_EDGES + e]);
    int pos = atomicAdd(&g_cursor[tar], 1);
    g_csrc[pos] = src;
}

// ------------- K3: pull-mode aggregation (warp per node, register acc) ---------
__global__ __launch_bounds__(256) void k_agg(float* __restrict__ out) {
    const int warp = (blockIdx.x * 256 + threadIdx.x) >> 5;
    const int lane = threadIdx.x & 31;
    if (warp >= N_NODES) return;
    const int n = warp;
    const int beg = g_rowptr[n];
    const int end = g_rowptr[n + 1];
    const float e0n = g_e0[n];
    const float es  = g_es[n];
    float2 fs = *(const float2*)&g_feature[(size_t)n * OUT_CH + lane * 2];
    float acc0 = es * fs.x, acc1 = es * fs.y, dsum = es;

    for (int j0 = beg; j0 < end; j0 += 32) {
        const int idx = j0 + lane;
        int src = 0;
        float ee = 0.f;
        if (idx < end) {
            src = __ldg(&g_csrc[idx]);
            ee  = __expf(lrelu(e0n + __ldg(&g_e1[src])));
        }
        const int cnt = min(32, end - j0);
        for (int j = 0; j < cnt; j++) {
            int   s = __shfl_sync(0xffffffffu, src, j);
            float w = __shfl_sync(0xffffffffu, ee,  j);
            float2 f = *(const float2*)&g_feature[(size_t)s * OUT_CH + lane * 2];
            acc0 += w * f.x;
            acc1 += w * f.y;
            dsum += w;
        }
    }
    const float rd = 1.0f / dsum;
    *(float2*)&out[(size_t)n * OUT_CH + lane * 2] = make_float2(acc0 * rd, acc1 * rd);
}

// -------------------------------------------------------------------------------
extern "C" void kernel_launch(void* const* d_in, const int* in_sizes, int n_in,
                              void* d_out, int out_size) {
    const float* x   = (const float*)d_in[0];
    const int*   ei  = (const int*)d_in[1];   // int32 (JAX x64 disabled)
    const float* W   = (const float*)d_in[2];
    const float* b   = (const float*)d_in[3];
    const float* att = (const float*)d_in[4];
    float* out = (float*)d_out;

    // one-time host objects (no device memory involved)
    static cudaStream_t s2 = nullptr;
    static cudaEvent_t evF = nullptr, evJ = nullptr;
    if (s2 == nullptr) {
        cudaStreamCreate(&s2);
        cudaEventCreateWithFlags(&evF, cudaEventDisableTiming);
        cudaEventCreateWithFlags(&evJ, cudaEventDisableTiming);
    }
    cudaFuncSetAttribute(k_gemm_tc, cudaFuncAttributeMaxDynamicSharedMemorySize, DYN_BYTES);

    // fork: edge-index chain on s2, GEMM chain on the main stream
    cudaEventRecord(evF, 0);
    cudaStreamWaitEvent(s2, evF, 0);
    k_zero   <<<NB_SCAN, 256, 0, s2>>>();
    k_hist   <<<(N_EDGES + 255) / 256, 256, 0, s2>>>(ei);
    k_scan1  <<<NB_SCAN, 256, 0, s2>>>();
    k_scan23 <<<NB_SCAN, 256, 0, s2>>>();
    k_scatter<<<(N_EDGES + 255) / 256, 256, 0, s2>>>(ei);
    cudaEventRecord(evJ, s2);

    k_wconv  <<<16, 256>>>(W);
    k_gemm_tc<<<(N_NODES + 127) / 128, 256, DYN_BYTES>>>(x, b, att);

    // join, then aggregate
    cudaStreamWaitEvent(0, evJ, 0);
    k_agg<<<(N_NODES * 32 + 255) / 256, 256>>>(out);
}

// round 12
// speedup vs baseline: 2.0567x; 1.0008x over previous
#include <cuda_runtime.h>
#include <cuda_bf16.h>
#include <cstdint>

#define N_NODES 50000
#define N_EDGES 800000
#define IN_CH   256
#define OUT_CH  64
#define NEG_SLOPE 0.2f
#define NB_SCAN 196   // ceil(N_NODES/256)

// dynamic smem: sB4[64][36] uint4 (interleaved bh/bl quads) | xs[2][128][36] floats
#define SB_UINT4   (64 * 36)                      // 36864 B
#define XS_FLOATS  (2 * 128 * 36)                 // 36864 B
#define DYN_BYTES  (SB_UINT4 * 16 + XS_FLOATS * 4)   // 73728

// ---------------- scratch (device globals; no allocations allowed) -------------
__device__ float    g_feature[N_NODES * OUT_CH];
__device__ float    g_e0[N_NODES];
__device__ float    g_e1[N_NODES];
__device__ float    g_es[N_NODES];              // exp(self logit)
__device__ uint4    g_Wi[2 * 64 * 32];          // [half][n][kc*4+tig] = {bh0,bh1,bl0,bl1}
__device__ int      g_cnt[N_NODES];
__device__ int      g_rowptr[N_NODES + 1];
__device__ int      g_cursor[N_NODES];
__device__ int      g_csrc[N_EDGES];
__device__ int      g_bsum[NB_SCAN];

__device__ __forceinline__ float lrelu(float v) {
    return v > 0.0f ? v : NEG_SLOPE * v;
}
__device__ __forceinline__ uint32_t smem_u32(const void* p) {
    uint32_t a;
    asm("{ .reg .u64 t; cvta.to.shared.u64 t, %1; cvt.u32.u64 %0, t; }" : "=r"(a) : "l"(p));
    return a;
}
__device__ __forceinline__ void cp16(void* dst, const void* src) {
    asm volatile("cp.async.cg.shared.global [%0], [%1], 16;"
                 :: "r"(smem_u32(dst)), "l"(src) : "memory");
}
#define CP_COMMIT() asm volatile("cp.async.commit_group;" ::: "memory")
#define CP_WAIT(n)  asm volatile("cp.async.wait_group %0;" :: "n"(n) : "memory")

// pack two floats (even, odd) into bf16x2 (even in low half)
__device__ __forceinline__ uint32_t pack_bf16(float e, float o) {
    uint32_t d;
    asm("cvt.rn.bf16x2.f32 %0, %1, %2;" : "=r"(d) : "f"(o), "f"(e));
    return d;
}
__device__ __forceinline__ float bf16lo_val(uint32_t w) { return __uint_as_float(w << 16); }
__device__ __forceinline__ float bf16hi_val(uint32_t w) { return __uint_as_float(w & 0xFFFF0000u); }

// m16n8k16 row.col bf16 HMMA (target-generic; tcgen05 unavailable on this build)
__device__ __forceinline__ void mma_bf16(float* c, const uint32_t* a, uint32_t b0, uint32_t b1) {
    asm volatile(
        "mma.sync.aligned.m16n8k16.row.col.f32.bf16.bf16.f32 "
        "{%0,%1,%2,%3}, {%4,%5,%6,%7}, {%8,%9}, {%0,%1,%2,%3};"
        : "+f"(c[0]), "+f"(c[1]), "+f"(c[2]), "+f"(c[3])
        : "r"(a[0]), "r"(a[1]), "r"(a[2]), "r"(a[3]), "r"(b0), "r"(b1));
}

// ------------- K0a: W -> interleaved bf16 hi/lo quads --------------------------
__global__ __launch_bounds__(256) void k_wconv(const float* __restrict__ W) {
    int idx = blockIdx.x * 256 + threadIdx.x;    // 0..4095
    int half = idx >> 11, rem = idx & 2047;
    int n = rem >> 5, m = rem & 31;
    int kc = m >> 2, tig = m & 3;
    int kw = kc * 8 + tig;
    int k1 = half * 128 + 2 * kw;
    int k2 = k1 + 8;
    float a0 = W[n * 256 + k1], a1 = W[n * 256 + k1 + 1];
    float b0 = W[n * 256 + k2], b1 = W[n * 256 + k2 + 1];
    uint32_t h1 = pack_bf16(a0, a1);
    uint32_t h2 = pack_bf16(b0, b1);
    uint32_t l1 = pack_bf16(a0 - bf16lo_val(h1), a1 - bf16hi_val(h1));
    uint32_t l2 = pack_bf16(b0 - bf16lo_val(h2), b1 - bf16hi_val(h2));
    g_Wi[half * 2048 + n * 32 + m] = make_uint4(h1, h2, l1, l2);
}

// ------------- K0b: zero in-degree histogram -----------------------------------
__global__ __launch_bounds__(256) void k_zero() {
    int i = blockIdx.x * 256 + threadIdx.x;
    if (i < N_NODES) g_cnt[i] = 0;
}

// ------------- K1: HMMA projection, warp-autonomous cp.async pipeline ----------
// Each warp stages + consumes its OWN 16 x-rows (depth-2 cp.async groups, warp-
// local wait). Only 3 CTA barriers total (around the two B-half fills).
__global__ __launch_bounds__(256, 3) void k_gemm_tc(const float* __restrict__ x,
                                                    const float* __restrict__ b,
                                                    const float* __restrict__ att) {
    extern __shared__ __align__(16) uint4 dyn4[];
    uint4* sB4 = dyn4;                                 // [n*36 + kc*4 + tig]
    float* xsf = (float*)(dyn4 + SB_UINT4);            // [buf*128*36 + row*36 + k]

    const int tid  = threadIdx.x;
    const int wid  = tid >> 5;
    const int lane = tid & 31;
    const int g    = lane >> 2;
    const int tig  = lane & 3;

    const int base = blockIdx.x * 128 + wid * 16;
    const int r0 = base + g;
    const int r1 = base + g + 8;
    const bool v0 = r0 < N_NODES;
    const bool v1 = r1 < N_NODES;

    // per-warp cp.async assignment: lane -> (row-in-warp, 16-float half)
    const int rloc    = wid * 16 + (lane >> 1);    // global-local row 0..127
    const int half16  = (lane & 1) * 16;
    const int gr      = min(blockIdx.x * 128 + rloc, N_NODES - 1);
    const float* xsrc = x + (size_t)gr * IN_CH + half16;

    float acc[8][4];
#pragma unroll
    for (int nt = 0; nt < 8; nt++)
#pragma unroll
        for (int i = 0; i < 4; i++) acc[nt][i] = 0.f;

    auto fillB = [&](int h) {
#pragma unroll
        for (int i = 0; i < 8; i++) {
            int s = tid * 8 + i;                   // 0..2047
            sB4[(s >> 5) * 36 + (s & 31)] = g_Wi[h * 2048 + s];
        }
    };
    auto issue = [&](int c) {
        float* dst = &xsf[(c & 1) * (128 * 36) + rloc * 36 + half16];
        const float* src = xsrc + c * 32;
#pragma unroll
        for (int i = 0; i < 4; i++) cp16(dst + i * 4, src + i * 4);
        CP_COMMIT();
    };

    issue(0);
    issue(1);
    fillB(0);
    __syncthreads();                       // B half0 visible (also covers xs init)

    for (int c = 0; c < 8; c++) {
        if (c == 4) {                      // B half switch: the only mid barriers
            __syncthreads();
            fillB(1);
            __syncthreads();
        }
        if (c == 7) { CP_WAIT(0); } else { CP_WAIT(1); }
        __syncwarp();                      // warp-local visibility of staged chunk

        const float* xb = xsf + (c & 1) * (128 * 36);
        const int kh = (c & 3) * 2;
#pragma unroll
        for (int kk = 0; kk < 2; kk++) {
            const int kloc = kk * 16 + tig * 2;
            const float* row0 = xb + (wid * 16 + g) * 36;
            const float* row1 = xb + (wid * 16 + g + 8) * 36;
            float2 a0 = *(const float2*)(row0 + kloc);
            float2 a4 = *(const float2*)(row0 + kloc + 8);
            float2 c0 = *(const float2*)(row1 + kloc);
            float2 c4 = *(const float2*)(row1 + kloc + 8);
            uint32_t ah[4], al[4];
            ah[0] = pack_bf16(a0.x, a0.y);
            ah[1] = pack_bf16(c0.x, c0.y);
            ah[2] = pack_bf16(a4.x, a4.y);
            ah[3] = pack_bf16(c4.x, c4.y);
            al[0] = pack_bf16(a0.x - bf16lo_val(ah[0]), a0.y - bf16hi_val(ah[0]));
            al[1] = pack_bf16(c0.x - bf16lo_val(ah[1]), c0.y - bf16hi_val(ah[1]));
            al[2] = pack_bf16(a4.x - bf16lo_val(ah[2]), a4.y - bf16hi_val(ah[2]));
            al[3] = pack_bf16(c4.x - bf16lo_val(ah[3]), c4.y - bf16hi_val(ah[3]));
            const int kq = (kh + kk) * 4 + tig;
#pragma unroll
            for (int nt = 0; nt < 8; nt++) {
                uint4 B = sB4[(nt * 8 + g) * 36 + kq];   // one LDS.128
                mma_bf16(acc[nt], ah, B.x, B.y);
                mma_bf16(acc[nt], al, B.x, B.y);
                mma_bf16(acc[nt], ah, B.z, B.w);
            }
        }
        // re-stage this buffer for chunk c+2 (≥24 MMA issues since last LDS of
        // this buffer -> LDS long drained before async write lands)
        if (c < 6) issue(c + 2);
    }

    // ---- epilogue: bias, e0/e1 reduce, feature + self-exp stores ----
    float e0a = 0.f, e1a = 0.f, e0b = 0.f, e1b = 0.f;
#pragma unroll
    for (int nt = 0; nt < 8; nt++) {
        int col = nt * 8 + tig * 2;
        float bi0 = __ldg(&b[col]);
        float bi1 = __ldg(&b[col + 1]);
        float at00 = __ldg(&att[col * 2 + 0]),   at01 = __ldg(&att[col * 2 + 1]);
        float at10 = __ldg(&att[(col + 1) * 2]), at11 = __ldg(&att[(col + 1) * 2 + 1]);
        acc[nt][0] += bi0; acc[nt][1] += bi1;
        acc[nt][2] += bi0; acc[nt][3] += bi1;
        e0a += acc[nt][0] * at00 + acc[nt][1] * at10;
        e1a += acc[nt][0] * at01 + acc[nt][1] * at11;
        e0b += acc[nt][2] * at00 + acc[nt][3] * at10;
        e1b += acc[nt][2] * at01 + acc[nt][3] * at11;
    }
#pragma unroll
    for (int o = 1; o <= 2; o <<= 1) {
        e0a += __shfl_xor_sync(0xffffffffu, e0a, o);
        e1a += __shfl_xor_sync(0xffffffffu, e1a, o);
        e0b += __shfl_xor_sync(0xffffffffu, e0b, o);
        e1b += __shfl_xor_sync(0xffffffffu, e1b, o);
    }
#pragma unroll
    for (int nt = 0; nt < 8; nt++) {
        int col = nt * 8 + tig * 2;
        if (v0) *(float2*)&g_feature[(size_t)r0 * OUT_CH + col] = make_float2(acc[nt][0], acc[nt][1]);
        if (v1) *(float2*)&g_feature[(size_t)r1 * OUT_CH + col] = make_float2(acc[nt][2], acc[nt][3]);
    }
    if (tig == 0) {
        if (v0) { g_e0[r0] = e0a; g_e1[r0] = e1a; g_es[r0] = __expf(lrelu(e0a + e1a)); }
        if (v1) { g_e0[r1] = e0b; g_e1[r1] = e1b; g_es[r1] = __expf(lrelu(e0b + e1b)); }
    }
}

// ------------- K2a: in-degree histogram ----------------------------------------
__global__ __launch_bounds__(256) void k_hist(const int* __restrict__ ei) {
    int e = blockIdx.x * 256 + threadIdx.x;
    if (e >= N_EDGES) return;
    atomicAdd(&g_cnt[__ldg(&ei[e])], 1);
}

// ------------- K2b1: per-block sums --------------------------------------------
__global__ __launch_bounds__(256) void k_scan1() {
    __shared__ int ws[8];
    const int t = threadIdx.x, lane = t & 31, w = t >> 5;
    const int i = blockIdx.x * 256 + t;
    int v = (i < N_NODES) ? g_cnt[i] : 0;
#pragma unroll
    for (int o = 16; o; o >>= 1) v += __shfl_xor_sync(0xffffffffu, v, o);
    if (lane == 0) ws[w] = v;
    __syncthreads();
    if (t == 0) {
        int s = 0;
#pragma unroll
        for (int j = 0; j < 8; j++) s += ws[j];
        g_bsum[blockIdx.x] = s;
    }
}

// ------------- K2b2: fused block-offset + local scan -> rowptr, cursor ---------
__global__ __launch_bounds__(256) void k_scan23() {
    __shared__ int ws[8];
    __shared__ int sboff;
    const int t = threadIdx.x, lane = t & 31, w = t >> 5;

    int v = (t < NB_SCAN && t < blockIdx.x) ? g_bsum[t] : 0;
#pragma unroll
    for (int o = 16; o; o >>= 1) v += __shfl_xor_sync(0xffffffffu, v, o);
    if (lane == 0) ws[w] = v;
    __syncthreads();
    if (t == 0) {
        int s = 0;
#pragma unroll
        for (int j = 0; j < 8; j++) s += ws[j];
        sboff = s;
    }
    __syncthreads();
    const int boff = sboff;
    __syncthreads();

    const int i = blockIdx.x * 256 + t;
    int c = (i < N_NODES) ? g_cnt[i] : 0;
    int inc = c;
#pragma unroll
    for (int o = 1; o < 32; o <<= 1) {
        int u = __shfl_up_sync(0xffffffffu, inc, o);
        if (lane >= o) inc += u;
    }
    if (lane == 31) ws[w] = inc;
    __syncthreads();
    if (w == 0) {
        int s = (lane < 8) ? ws[lane] : 0;
#pragma unroll
        for (int o = 1; o < 8; o <<= 1) {
            int u = __shfl_up_sync(0xffffffffu, s, o);
            if (lane >= o) s += u;
        }
        if (lane < 8) ws[lane] = s;
    }
    __syncthreads();
    int pos = boff + (w ? ws[w - 1] : 0) + inc - c;
    if (i < N_NODES) {
        g_rowptr[i] = pos;
        g_cursor[i] = pos;
    }
    if (blockIdx.x == 0 && t == 0) g_rowptr[N_NODES] = N_EDGES;
}

// ------------- K2c: scatter src indices into CSR slots -------------------------
__global__ __launch_bounds__(256) void k_scatter(const int* __restrict__ ei) {
    int e = blockIdx.x * 256 + threadIdx.x;
    if (e >= N_EDGES) return;
    int tar = __ldg(&ei[e]);
    int src = __ldg(&ei[N_EDGES + e]);
    int pos = atomicAdd(&g_cursor[tar], 1);
    g_csrc[pos] = src;
}

// ------------- K3: pull-mode aggregation (warp per node, register acc) ---------
__global__ __launch_bounds__(256) void k_agg(float* __restrict__ out) {
    const int warp = (blockIdx.x * 256 + threadIdx.x) >> 5;
    const int lane = threadIdx.x & 31;
    if (warp >= N_NODES) return;
    const int n = warp;
    const int beg = g_rowptr[n];
    const int end = g_rowptr[n + 1];
    const float e0n = g_e0[n];
    const float es  = g_es[n];
    float2 fs = *(const float2*)&g_feature[(size_t)n * OUT_CH + lane * 2];
    float acc0 = es * fs.x, acc1 = es * fs.y, dsum = es;

    for (int j0 = beg; j0 < end; j0 += 32) {
        const int idx = j0 + lane;
        int src = 0;
        float ee = 0.f;
        if (idx < end) {
            src = __ldg(&g_csrc[idx]);
            ee  = __expf(lrelu(e0n + __ldg(&g_e1[src])));
        }
        const int cnt = min(32, end - j0);
#pragma unroll 4
        for (int j = 0; j < cnt; j++) {
            int   s = __shfl_sync(0xffffffffu, src, j);
            float w = __shfl_sync(0xffffffffu, ee,  j);
            float2 f = *(const float2*)&g_feature[(size_t)s * OUT_CH + lane * 2];
            acc0 += w * f.x;
            acc1 += w * f.y;
            dsum += w;
        }
    }
    const float rd = 1.0f / dsum;
    *(float2*)&out[(size_t)n * OUT_CH + lane * 2] = make_float2(acc0 * rd, acc1 * rd);
}

// -------------------------------------------------------------------------------
extern "C" void kernel_launch(void* const* d_in, const int* in_sizes, int n_in,
                              void* d_out, int out_size) {
    const float* x   = (const float*)d_in[0];
    const int*   ei  = (const int*)d_in[1];   // int32 (JAX x64 disabled)
    const float* W   = (const float*)d_in[2];
    const float* b   = (const float*)d_in[3];
    const float* att = (const float*)d_in[4];
    float* out = (float*)d_out;

    static cudaStream_t s2 = nullptr;
    static cudaEvent_t evF = nullptr, evJ = nullptr;
    if (s2 == nullptr) {
        cudaStreamCreate(&s2);
        cudaEventCreateWithFlags(&evF, cudaEventDisableTiming);
        cudaEventCreateWithFlags(&evJ, cudaEventDisableTiming);
    }
    cudaFuncSetAttribute(k_gemm_tc, cudaFuncAttributeMaxDynamicSharedMemorySize, DYN_BYTES);

    // fork: edge-index chain on s2, GEMM chain on the main stream
    cudaEventRecord(evF, 0);
    cudaStreamWaitEvent(s2, evF, 0);
    k_zero   <<<NB_SCAN, 256, 0, s2>>>();
    k_hist   <<<(N_EDGES + 255) / 256, 256, 0, s2>>>(ei);
    k_scan1  <<<NB_SCAN, 256, 0, s2>>>();
    k_scan23 <<<NB_SCAN, 256, 0, s2>>>();
    k_scatter<<<(N_EDGES + 255) / 256, 256, 0, s2>>>(ei);
    cudaEventRecord(evJ, s2);

    k_wconv  <<<16, 256>>>(W);
    k_gemm_tc<<<(N_NODES + 127) / 128, 256, DYN_BYTES>>>(x, b, att);

    // join, then aggregate
    cudaStreamWaitEvent(0, evJ, 0);
    k_agg<<<(N_NODES * 32 + 255) / 256, 256>>>(out);
}

// round 13
// speedup vs baseline: 2.2083x; 1.0737x over previous
#include <cuda_runtime.h>
#include <cuda_bf16.h>
#include <cstdint>

#define N_NODES 50000
#define N_EDGES 800000
#define IN_CH   256
#define OUT_CH  64
#define NEG_SLOPE 0.2f
#define NB_SCAN 196   // ceil(N_NODES/256)

// dynamic smem layout (uint4 units): sX[8192] (128KB) | sB[64][68] (68KB) | mbar[8]
#define SX_U4     8192
#define SB_U4     (64 * 68)
#define DYN_BYTES (SX_U4 * 16 + SB_U4 * 16 + 64)   // 200768

// ---------------- scratch (device globals; no allocations allowed) -------------
__device__ float    g_feature[N_NODES * OUT_CH];
__device__ float    g_e0[N_NODES];
__device__ float    g_e1[N_NODES];
__device__ float    g_es[N_NODES];              // exp(self logit)
__device__ uint4    g_Wi[2 * 64 * 32];          // [half][n][kc*4+tig] = {bh0,bh1,bl0,bl1}
__device__ int      g_cnt[N_NODES];
__device__ int      g_rowptr[N_NODES + 1];
__device__ int      g_cursor[N_NODES];
__device__ int      g_csrc[N_EDGES];
__device__ int      g_bsum[NB_SCAN];

__device__ __forceinline__ float lrelu(float v) {
    return v > 0.0f ? v : NEG_SLOPE * v;
}
__device__ __forceinline__ uint32_t smem_u32(const void* p) {
    uint32_t a;
    asm("{ .reg .u64 t; cvta.to.shared.u64 t, %1; cvt.u32.u64 %0, t; }" : "=r"(a) : "l"(p));
    return a;
}

// pack two floats (even, odd) into bf16x2 (even in low half)
__device__ __forceinline__ uint32_t pack_bf16(float e, float o) {
    uint32_t d;
    asm("cvt.rn.bf16x2.f32 %0, %1, %2;" : "=r"(d) : "f"(o), "f"(e));
    return d;
}
__device__ __forceinline__ float bf16lo_val(uint32_t w) { return __uint_as_float(w << 16); }
__device__ __forceinline__ float bf16hi_val(uint32_t w) { return __uint_as_float(w & 0xFFFF0000u); }

// m16n8k16 row.col bf16 HMMA (target-generic; tcgen05 unavailable on this build)
__device__ __forceinline__ void mma_bf16(float* c, const uint32_t* a, uint32_t b0, uint32_t b1) {
    asm volatile(
        "mma.sync.aligned.m16n8k16.row.col.f32.bf16.bf16.f32 "
        "{%0,%1,%2,%3}, {%4,%5,%6,%7}, {%8,%9}, {%0,%1,%2,%3};"
        : "+f"(c[0]), "+f"(c[1]), "+f"(c[2]), "+f"(c[3])
        : "r"(a[0]), "r"(a[1]), "r"(a[2]), "r"(a[3]), "r"(b0), "r"(b1));
}

// ------------- K0a: W -> interleaved bf16 hi/lo quads --------------------------
__global__ __launch_bounds__(256) void k_wconv(const float* __restrict__ W) {
    int idx = blockIdx.x * 256 + threadIdx.x;    // 0..4095
    int half = idx >> 11, rem = idx & 2047;
    int n = rem >> 5, m = rem & 31;
    int kc = m >> 2, tig = m & 3;
    int kw = kc * 8 + tig;
    int k1 = half * 128 + 2 * kw;
    int k2 = k1 + 8;
    float a0 = W[n * 256 + k1], a1 = W[n * 256 + k1 + 1];
    float b0 = W[n * 256 + k2], b1 = W[n * 256 + k2 + 1];
    uint32_t h1 = pack_bf16(a0, a1);
    uint32_t h2 = pack_bf16(b0, b1);
    uint32_t l1 = pack_bf16(a0 - bf16lo_val(h1), a1 - bf16hi_val(h1));
    uint32_t l2 = pack_bf16(b0 - bf16lo_val(h2), b1 - bf16hi_val(h2));
    g_Wi[half * 2048 + n * 32 + m] = make_uint4(h1, h2, l1, l2);
}

// ------------- K0b: zero in-degree histogram -----------------------------------
__global__ __launch_bounds__(256) void k_zero() {
    int i = blockIdx.x * 256 + threadIdx.x;
    if (i < N_NODES) g_cnt[i] = 0;
}

// ------------- K1: HMMA projection, cp.async.bulk x staging --------------------
// 1 CTA/SM (197KB smem). Each warp bulk-copies its 16 contiguous x rows (16KB,
// ONE instruction) with per-warp mbarrier completion; computes full K=256.
__global__ __launch_bounds__(256) void k_gemm_tc(const float* __restrict__ x,
                                                 const float* __restrict__ b,
                                                 const float* __restrict__ att) {
    extern __shared__ __align__(16) uint4 dyn4[];
    float*    sXf  = (float*)dyn4;                       // [8 warps][16 rows][256]
    uint4*    sB4  = dyn4 + SX_U4;                       // [n][68]: q = half*32+kc*4+tig
    uint64_t* mbar = (uint64_t*)(dyn4 + SX_U4 + SB_U4);  // [8]

    const int tid  = threadIdx.x;
    const int wid  = tid >> 5;
    const int lane = tid & 31;
    const int g    = lane >> 2;
    const int tig  = lane & 3;

    // clamped per-warp row block (last CTA: duplicate warps write identical rows)
    const int base = min(blockIdx.x * 128 + wid * 16, N_NODES - 16);
    const int r0 = base + g;
    const int r1 = base + g + 8;

    // init per-warp mbarriers
    if (tid < 8) {
        asm volatile("mbarrier.init.shared.b64 [%0], 1;"
                     :: "r"(smem_u32(&mbar[tid])) : "memory");
    }
    __syncthreads();

    // one bulk copy per warp: 16 rows x 1KB contiguous
    if (lane == 0) {
        uint32_t mb  = smem_u32(&mbar[wid]);
        uint32_t dst = smem_u32(sXf) + (uint32_t)wid * 16384u;
        const float* src = x + (size_t)base * IN_CH;
        asm volatile("mbarrier.arrive.expect_tx.shared.b64 _, [%0], %1;"
                     :: "r"(mb), "r"(16384u) : "memory");
        asm volatile("cp.async.bulk.shared::cluster.global.mbarrier::complete_tx::bytes "
                     "[%0], [%1], %2, [%3];"
                     :: "r"(dst), "l"(src), "r"(16384u), "r"(mb) : "memory");
    }

    // fill B (both halves) while DMA flies: 4096 quads / 256 threads
#pragma unroll
    for (int i = 0; i < 16; i++) {
        int s = tid + i * 256;
        int half = s >> 11, rem = s & 2047;
        int n = rem >> 5, m = rem & 31;
        sB4[n * 68 + half * 32 + m] = g_Wi[s];
    }
    __syncthreads();                                     // B visible to all

    // wait own warp's x block
    {
        uint32_t mb = smem_u32(&mbar[wid]);
        asm volatile(
            "{ .reg .pred p;\n"
            "W_%=: mbarrier.try_wait.parity.shared.b64 p, [%0], 0;\n"
            " @p bra D_%=;\n"
            " bra W_%=;\n"
            "D_%=: }"
            :: "r"(mb) : "memory");
    }
    __syncwarp();

    float acc[8][4];
#pragma unroll
    for (int nt = 0; nt < 8; nt++)
#pragma unroll
        for (int i = 0; i < 4; i++) acc[nt][i] = 0.f;

    const float* row0 = sXf + wid * 4096 + g * 256;
    const float* row1 = sXf + wid * 4096 + (g + 8) * 256;

    for (int c = 0; c < 8; c++) {
#pragma unroll
        for (int kk = 0; kk < 2; kk++) {
            const int kloc = c * 32 + kk * 16 + tig * 2;
            float2 a0 = *(const float2*)(row0 + kloc);
            float2 a4 = *(const float2*)(row0 + kloc + 8);
            float2 c0 = *(const float2*)(row1 + kloc);
            float2 c4 = *(const float2*)(row1 + kloc + 8);
            uint32_t ah[4], al[4];
            ah[0] = pack_bf16(a0.x, a0.y);
            ah[1] = pack_bf16(c0.x, c0.y);
            ah[2] = pack_bf16(a4.x, a4.y);
            ah[3] = pack_bf16(c4.x, c4.y);
            al[0] = pack_bf16(a0.x - bf16lo_val(ah[0]), a0.y - bf16hi_val(ah[0]));
            al[1] = pack_bf16(c0.x - bf16lo_val(ah[1]), c0.y - bf16hi_val(ah[1]));
            al[2] = pack_bf16(a4.x - bf16lo_val(ah[2]), a4.y - bf16hi_val(ah[2]));
            al[3] = pack_bf16(c4.x - bf16lo_val(ah[3]), c4.y - bf16hi_val(ah[3]));
            const int qidx = (c >> 2) * 32 + ((c & 3) * 2 + kk) * 4 + tig;
#pragma unroll
            for (int grp = 0; grp < 2; grp++) {
                const int nb = grp * 4;
                uint4 q0 = sB4[(nb * 8 +  0 + g) * 68 + qidx];
                uint4 q1 = sB4[(nb * 8 +  8 + g) * 68 + qidx];
                uint4 q2 = sB4[(nb * 8 + 16 + g) * 68 + qidx];
                uint4 q3 = sB4[(nb * 8 + 24 + g) * 68 + qidx];
                // dependent MMAs on same acc are 4 apart
                mma_bf16(acc[nb + 0], ah, q0.x, q0.y);
                mma_bf16(acc[nb + 1], ah, q1.x, q1.y);
                mma_bf16(acc[nb + 2], ah, q2.x, q2.y);
                mma_bf16(acc[nb + 3], ah, q3.x, q3.y);
                mma_bf16(acc[nb + 0], al, q0.x, q0.y);
                mma_bf16(acc[nb + 1], al, q1.x, q1.y);
                mma_bf16(acc[nb + 2], al, q2.x, q2.y);
                mma_bf16(acc[nb + 3], al, q3.x, q3.y);
                mma_bf16(acc[nb + 0], ah, q0.z, q0.w);
                mma_bf16(acc[nb + 1], ah, q1.z, q1.w);
                mma_bf16(acc[nb + 2], ah, q2.z, q2.w);
                mma_bf16(acc[nb + 3], ah, q3.z, q3.w);
            }
        }
    }

    // ---- epilogue: bias, e0/e1 reduce, feature + self-exp stores ----
    float e0a = 0.f, e1a = 0.f, e0b = 0.f, e1b = 0.f;
#pragma unroll
    for (int nt = 0; nt < 8; nt++) {
        int col = nt * 8 + tig * 2;
        float bi0 = __ldg(&b[col]);
        float bi1 = __ldg(&b[col + 1]);
        float at00 = __ldg(&att[col * 2 + 0]),   at01 = __ldg(&att[col * 2 + 1]);
        float at10 = __ldg(&att[(col + 1) * 2]), at11 = __ldg(&att[(col + 1) * 2 + 1]);
        acc[nt][0] += bi0; acc[nt][1] += bi1;
        acc[nt][2] += bi0; acc[nt][3] += bi1;
        e0a += acc[nt][0] * at00 + acc[nt][1] * at10;
        e1a += acc[nt][0] * at01 + acc[nt][1] * at11;
        e0b += acc[nt][2] * at00 + acc[nt][3] * at10;
        e1b += acc[nt][2] * at01 + acc[nt][3] * at11;
    }
#pragma unroll
    for (int o = 1; o <= 2; o <<= 1) {
        e0a += __shfl_xor_sync(0xffffffffu, e0a, o);
        e1a += __shfl_xor_sync(0xffffffffu, e1a, o);
        e0b += __shfl_xor_sync(0xffffffffu, e0b, o);
        e1b += __shfl_xor_sync(0xffffffffu, e1b, o);
    }
#pragma unroll
    for (int nt = 0; nt < 8; nt++) {
        int col = nt * 8 + tig * 2;
        *(float2*)&g_feature[(size_t)r0 * OUT_CH + col] = make_float2(acc[nt][0], acc[nt][1]);
        *(float2*)&g_feature[(size_t)r1 * OUT_CH + col] = make_float2(acc[nt][2], acc[nt][3]);
    }
    if (tig == 0) {
        g_e0[r0] = e0a; g_e1[r0] = e1a; g_es[r0] = __expf(lrelu(e0a + e1a));
        g_e0[r1] = e0b; g_e1[r1] = e1b; g_es[r1] = __expf(lrelu(e0b + e1b));
    }
}

// ------------- K2a: in-degree histogram ----------------------------------------
__global__ __launch_bounds__(256) void k_hist(const int* __restrict__ ei) {
    int e = blockIdx.x * 256 + threadIdx.x;
    if (e >= N_EDGES) return;
    atomicAdd(&g_cnt[__ldg(&ei[e])], 1);
}

// ------------- K2b1: per-block sums --------------------------------------------
__global__ __launch_bounds__(256) void k_scan1() {
    __shared__ int ws[8];
    const int t = threadIdx.x, lane = t & 31, w = t >> 5;
    const int i = blockIdx.x * 256 + t;
    int v = (i < N_NODES) ? g_cnt[i] : 0;
#pragma unroll
    for (int o = 16; o; o >>= 1) v += __shfl_xor_sync(0xffffffffu, v, o);
    if (lane == 0) ws[w] = v;
    __syncthreads();
    if (t == 0) {
        int s = 0;
#pragma unroll
        for (int j = 0; j < 8; j++) s += ws[j];
        g_bsum[blockIdx.x] = s;
    }
}

// ------------- K2b2: fused block-offset + local scan -> rowptr, cursor ---------
__global__ __launch_bounds__(256) void k_scan23() {
    __shared__ int ws[8];
    __shared__ int sboff;
    const int t = threadIdx.x, lane = t & 31, w = t >> 5;

    int v = (t < NB_SCAN && t < blockIdx.x) ? g_bsum[t] : 0;
#pragma unroll
    for (int o = 16; o; o >>= 1) v += __shfl_xor_sync(0xffffffffu, v, o);
    if (lane == 0) ws[w] = v;
    __syncthreads();
    if (t == 0) {
        int s = 0;
#pragma unroll
        for (int j = 0; j < 8; j++) s += ws[j];
        sboff = s;
    }
    __syncthreads();
    const int boff = sboff;
    __syncthreads();

    const int i = blockIdx.x * 256 + t;
    int c = (i < N_NODES) ? g_cnt[i] : 0;
    int inc = c;
#pragma unroll
    for (int o = 1; o < 32; o <<= 1) {
        int u = __shfl_up_sync(0xffffffffu, inc, o);
        if (lane >= o) inc += u;
    }
    if (lane == 31) ws[w] = inc;
    __syncthreads();
    if (w == 0) {
        int s = (lane < 8) ? ws[lane] : 0;
#pragma unroll
        for (int o = 1; o < 8; o <<= 1) {
            int u = __shfl_up_sync(0xffffffffu, s, o);
            if (lane >= o) s += u;
        }
        if (lane < 8) ws[lane] = s;
    }
    __syncthreads();
    int pos = boff + (w ? ws[w - 1] : 0) + inc - c;
    if (i < N_NODES) {
        g_rowptr[i] = pos;
        g_cursor[i] = pos;
    }
    if (blockIdx.x == 0 && t == 0) g_rowptr[N_NODES] = N_EDGES;
}

// ------------- K2c: scatter src indices into CSR slots -------------------------
__global__ __launch_bounds__(256) void k_scatter(const int* __restrict__ ei) {
    int e = blockIdx.x * 256 + threadIdx.x;
    if (e >= N_EDGES) return;
    int tar = __ldg(&ei[e]);
    int src = __ldg(&ei[N_EDGES + e]);
    int pos = atomicAdd(&g_cursor[tar], 1);
    g_csrc[pos] = src;
}

// ------------- K3: pull aggregation, half-warp per edge ------------------------
// 16 lanes x float4 per edge; halves process even/odd edges, combined via
// shfl_xor(16). Register softmax denominator; no RED, no normalize pass.
__global__ __launch_bounds__(256) void k_agg(float* __restrict__ out) {
    const int warp = (blockIdx.x * 256 + threadIdx.x) >> 5;
    const int lane = threadIdx.x & 31;
    if (warp >= N_NODES) return;
    const int h  = lane >> 4;          // half id
    const int sl = lane & 15;          // slot in half
    const int n = warp;
    const int beg = g_rowptr[n];
    const int end = g_rowptr[n + 1];
    const float e0n = g_e0[n];
    const float es  = g_es[n];

    float4 fs = *(const float4*)&g_feature[(size_t)n * OUT_CH + sl * 4];
    const float w0 = (h == 0) ? es : 0.f;          // self term in half 0 only
    float ax = w0 * fs.x, ay = w0 * fs.y, az = w0 * fs.z, aw = w0 * fs.w;
    float dsum = w0;

    for (int j0 = beg; j0 < end; j0 += 32) {
        const int idx = j0 + lane;
        int src = 0;
        float ee = 0.f;
        if (idx < end) {
            src = __ldg(&g_csrc[idx]);
            ee  = __expf(lrelu(e0n + __ldg(&g_e1[src])));
        }
        int cnt = end - j0; if (cnt > 32) cnt = 32;
        const int np = (cnt + 1) >> 1;             // uniform across halves
#pragma unroll 4
        for (int jj = 0; jj < np; jj++) {
            const int j = jj * 2 + h;              // lanes >= cnt carry ee=0
            int   s = __shfl_sync(0xffffffffu, src, j);
            float w = __shfl_sync(0xffffffffu, ee,  j);
            float4 f = *(const float4*)&g_feature[(size_t)s * OUT_CH + sl * 4];
            ax += w * f.x; ay += w * f.y; az += w * f.z; aw += w * f.w;
            dsum += w;
        }
    }
    // combine halves
    ax += __shfl_xor_sync(0xffffffffu, ax, 16);
    ay += __shfl_xor_sync(0xffffffffu, ay, 16);
    az += __shfl_xor_sync(0xffffffffu, az, 16);
    aw += __shfl_xor_sync(0xffffffffu, aw, 16);
    dsum += __shfl_xor_sync(0xffffffffu, dsum, 16);
    if (h == 0) {
        const float rd = 1.0f / dsum;
        *(float4*)&out[(size_t)n * OUT_CH + sl * 4] =
            make_float4(ax * rd, ay * rd, az * rd, aw * rd);
    }
}

// -------------------------------------------------------------------------------
extern "C" void kernel_launch(void* const* d_in, const int* in_sizes, int n_in,
                              void* d_out, int out_size) {
    const float* x   = (const float*)d_in[0];
    const int*   ei  = (const int*)d_in[1];   // int32 (JAX x64 disabled)
    const float* W   = (const float*)d_in[2];
    const float* b   = (const float*)d_in[3];
    const float* att = (const float*)d_in[4];
    float* out = (float*)d_out;

    static cudaStream_t s2 = nullptr;
    static cudaEvent_t evF = nullptr, evJ = nullptr;
    if (s2 == nullptr) {
        cudaStreamCreate(&s2);
        cudaEventCreateWithFlags(&evF, cudaEventDisableTiming);
        cudaEventCreateWithFlags(&evJ, cudaEventDisableTiming);
    }
    cudaFuncSetAttribute(k_gemm_tc, cudaFuncAttributeMaxDynamicSharedMemorySize, DYN_BYTES);

    // fork: edge-index chain on s2, GEMM chain on the main stream
    cudaEventRecord(evF, 0);
    cudaStreamWaitEvent(s2, evF, 0);
    k_zero   <<<NB_SCAN, 256, 0, s2>>>();
    k_hist   <<<(N_EDGES + 255) / 256, 256, 0, s2>>>(ei);
    k_scan1  <<<NB_SCAN, 256, 0, s2>>>();
    k_scan23 <<<NB_SCAN, 256, 0, s2>>>();
    k_scatter<<<(N_EDGES + 255) / 256, 256, 0, s2>>>(ei);
    cudaEventRecord(evJ, s2);

    k_wconv  <<<16, 256>>>(W);
    k_gemm_tc<<<(N_NODES + 127) / 128, 256, DYN_BYTES>>>(x, b, att);

    // join, then aggregate
    cudaStreamWaitEvent(0, evJ, 0);
    k_agg<<<(N_NODES * 32 + 255) / 256, 256>>>(out);
}